// round 1
// baseline (speedup 1.0000x reference)
#include <cuda_runtime.h>

#define B_ 2
#define L_ 2048
#define E_ 1024
#define H_ 16
#define D_ 64
#define BL_ (B_*L_)
#define BH_ (B_*H_)

// ---------------- scratch (device globals: no allocation allowed) ----------
__device__ float g_qkvt[(size_t)BL_ * 3*E_];   // xt @ Wt + bt   (4096 x 3072)
__device__ float g_qsks[(size_t)BL_ * 2*E_];   // xs @ Ws + bs   (4096 x 2048)
__device__ float g_Qp[(size_t)BH_ * L_ * 128]; // [bh][l][128]  (qt|qs) * 1/8
__device__ float g_Kp[(size_t)BH_ * L_ * 128]; // [bh][l][128]  (k1|k2)
__device__ float g_Vp[(size_t)BH_ * L_ * 64];  // [bh][l][64]
__device__ float g_y [(size_t)BL_ * E_];       // attention out, (B,L,E)

// ---------------- fp32 tiled GEMM: C[M,N] = A[M,K] @ W[K,N] + bias ---------
// M = gridDim.y*128 (all shapes here are multiples of 128 / K of 8).
__global__ __launch_bounds__(256) void gemm_bias(
    const float* __restrict__ A, const float* __restrict__ W,
    const float* __restrict__ bias, float* __restrict__ C,
    int N, int K)
{
    __shared__ float As[8][128];
    __shared__ float Bs[8][128];
    const int tid = threadIdx.x;
    const int tr = tid >> 4;          // 0..15
    const int tc = tid & 15;          // 0..15

    const float* Ab = A + (size_t)blockIdx.y * 128 * K;
    const float* Wb = W + (size_t)blockIdx.x * 128;

    float acc[8][8];
#pragma unroll
    for (int i = 0; i < 8; i++)
#pragma unroll
        for (int j = 0; j < 8; j++) acc[i][j] = 0.f;

    const int ar = tid >> 1;          // 0..127 (A tile row)
    const int ac = (tid & 1) * 4;     // 0 / 4
    const int wr = tid >> 5;          // 0..7   (W tile row)
    const int wc = (tid & 31) * 4;    // 0..124

    for (int k0 = 0; k0 < K; k0 += 8) {
        float4 av = *(const float4*)(Ab + (size_t)ar * K + k0 + ac);
        As[ac + 0][ar] = av.x; As[ac + 1][ar] = av.y;
        As[ac + 2][ar] = av.z; As[ac + 3][ar] = av.w;
        float4 wv = *(const float4*)(Wb + (size_t)(k0 + wr) * N + wc);
        *(float4*)&Bs[wr][wc] = wv;
        __syncthreads();

#pragma unroll
        for (int kk = 0; kk < 8; kk++) {
            float a[8], b[8];
#pragma unroll
            for (int i = 0; i < 8; i++) a[i] = As[kk][tr * 8 + i];
#pragma unroll
            for (int j = 0; j < 8; j++) b[j] = Bs[kk][tc * 8 + j];
#pragma unroll
            for (int i = 0; i < 8; i++)
#pragma unroll
                for (int j = 0; j < 8; j++)
                    acc[i][j] = fmaf(a[i], b[j], acc[i][j]);
        }
        __syncthreads();
    }

    const int grow0 = blockIdx.y * 128 + tr * 8;
    const int gcol0 = blockIdx.x * 128 + tc * 8;
#pragma unroll
    for (int i = 0; i < 8; i++) {
#pragma unroll
        for (int j = 0; j < 8; j += 4) {
            float4 o;
            o.x = acc[i][j + 0] + bias[gcol0 + j + 0];
            o.y = acc[i][j + 1] + bias[gcol0 + j + 1];
            o.z = acc[i][j + 2] + bias[gcol0 + j + 2];
            o.w = acc[i][j + 3] + bias[gcol0 + j + 3];
            *(float4*)(C + (size_t)(grow0 + i) * N + gcol0 + j) = o;
        }
    }
}

// ---------------- pack: build Q' (scaled), combined K', V per-head ---------
__global__ __launch_bounds__(256) void pack_kernel(
    const float* __restrict__ lam_ts, const float* __restrict__ lam_st,
    const float* __restrict__ lam_ss)
{
    const int bl = blockIdx.x;            // 0..BL_-1
    const int b = bl / L_, l = bl % L_;
    const int tid = threadIdx.x;
    const float lts = lam_ts[0], lst = lam_st[0], lss = lam_ss[0];
    const float* qkv = g_qkvt + (size_t)bl * 3 * E_;
    const float* qk  = g_qsks + (size_t)bl * 2 * E_;
    const float scale = 0.125f;           // 1/sqrt(64)

    for (int e = tid; e < H_ * 128; e += 256) {
        const int h = e >> 7, d = e & 127;
        const size_t o = ((size_t)(b * H_ + h) * L_ + l) * 128 + d;
        float qv, kv;
        if (d < 64) {
            const float qt  = qkv[h * 64 + d];
            const float kt  = qkv[E_ + h * 64 + d];
            const float ksv = qk [E_ + h * 64 + d];
            qv = qt;
            kv = kt + lts * ksv;
        } else {
            const int dd = d - 64;
            const float qs  = qk [h * 64 + dd];
            const float kt  = qkv[E_ + h * 64 + dd];
            const float ksv = qk [E_ + h * 64 + dd];
            qv = qs;
            kv = lst * kt + lss * ksv;
        }
        g_Qp[o] = qv * scale;
        g_Kp[o] = kv;
    }
    for (int e = tid; e < H_ * 64; e += 256) {
        const int h = e >> 6, d = e & 63;
        g_Vp[((size_t)(b * H_ + h) * L_ + l) * 64 + d] = qkv[2 * E_ + h * 64 + d];
    }
}

// ---------------- flash attention: dqk=128, dv=64, BQ=BK=64 ----------------
__global__ __launch_bounds__(256) void attn_kernel()
{
    extern __shared__ float sm[];
    float* Qs  = sm;               // [64][128]  natural
    float* Kst = sm + 64 * 128;    // [128][64]  k-major (transposed)
    float* Vs  = Kst + 128 * 64;   // [64][64]   natural
    float* Ps  = Vs + 64 * 64;     // [64][64]   natural

    const int bh  = blockIdx.y;
    const int q0  = blockIdx.x * 64;
    const int tid = threadIdx.x;
    const int tr  = tid >> 4;      // 0..15 -> q rows tr*4..+3
    const int tc  = tid & 15;      // 0..15 -> cols tc*4..+3

    const float* Qg = g_Qp + (size_t)bh * L_ * 128 + (size_t)q0 * 128;
    const float* Kg = g_Kp + (size_t)bh * L_ * 128;
    const float* Vg = g_Vp + (size_t)bh * L_ * 64;

    for (int i = tid * 4; i < 64 * 128; i += 1024)
        *(float4*)&Qs[i] = *(const float4*)&Qg[i];

    float m[4], lsum[4], O[4][4];
#pragma unroll
    for (int i = 0; i < 4; i++) {
        m[i] = -1e30f; lsum[i] = 0.f;
#pragma unroll
        for (int j = 0; j < 4; j++) O[i][j] = 0.f;
    }
    __syncthreads();

    for (int t = 0; t < L_ / 64; t++) {
        const float* Kt = Kg + (size_t)t * 64 * 128;
        const float* Vt = Vg + (size_t)t * 64 * 64;
        // K tile transposed into smem (conflict-free STS; global reads L2-cached)
        for (int idx = tid; idx < 2048; idx += 256) {
            const int col = idx & 63;       // key index
            const int kc  = idx >> 6;       // 0..31
            float4 v = *(const float4*)&Kt[col * 128 + kc * 4];
            Kst[(kc * 4 + 0) * 64 + col] = v.x;
            Kst[(kc * 4 + 1) * 64 + col] = v.y;
            Kst[(kc * 4 + 2) * 64 + col] = v.z;
            Kst[(kc * 4 + 3) * 64 + col] = v.w;
        }
        for (int i = tid * 4; i < 64 * 64; i += 1024)
            *(float4*)&Vs[i] = *(const float4*)&Vt[i];
        __syncthreads();

        // S[4][4] = Q(64x128) @ K^T
        float S[4][4];
#pragma unroll
        for (int i = 0; i < 4; i++)
#pragma unroll
            for (int j = 0; j < 4; j++) S[i][j] = 0.f;
#pragma unroll 4
        for (int kk = 0; kk < 128; kk++) {
            float b4[4];
            *(float4*)b4 = *(const float4*)&Kst[kk * 64 + tc * 4];
            float a4[4];
#pragma unroll
            for (int i = 0; i < 4; i++) a4[i] = Qs[(tr * 4 + i) * 128 + kk];
#pragma unroll
            for (int i = 0; i < 4; i++)
#pragma unroll
                for (int j = 0; j < 4; j++)
                    S[i][j] = fmaf(a4[i], b4[j], S[i][j]);
        }

        // online softmax per row (rows owned by 16 threads sharing tr)
#pragma unroll
        for (int i = 0; i < 4; i++) {
            float rm = fmaxf(fmaxf(S[i][0], S[i][1]), fmaxf(S[i][2], S[i][3]));
#pragma unroll
            for (int off = 8; off >= 1; off >>= 1)
                rm = fmaxf(rm, __shfl_xor_sync(0xffffffffu, rm, off));
            const float mn = fmaxf(m[i], rm);
            const float alpha = __expf(m[i] - mn);
            m[i] = mn;
            lsum[i] *= alpha;
#pragma unroll
            for (int j = 0; j < 4; j++) O[i][j] *= alpha;
            float rs = 0.f;
#pragma unroll
            for (int j = 0; j < 4; j++) { S[i][j] = __expf(S[i][j] - mn); rs += S[i][j]; }
#pragma unroll
            for (int off = 8; off >= 1; off >>= 1)
                rs += __shfl_xor_sync(0xffffffffu, rs, off);
            lsum[i] += rs;
            *(float4*)&Ps[(tr * 4 + i) * 64 + tc * 4] = *(float4*)&S[i][0];
        }
        __syncthreads();

        // O += P(64x64) @ V(64x64)
#pragma unroll 4
        for (int kk = 0; kk < 64; kk++) {
            float b4[4];
            *(float4*)b4 = *(const float4*)&Vs[kk * 64 + tc * 4];
            float a4[4];
#pragma unroll
            for (int i = 0; i < 4; i++) a4[i] = Ps[(tr * 4 + i) * 64 + kk];
#pragma unroll
            for (int i = 0; i < 4; i++)
#pragma unroll
                for (int j = 0; j < 4; j++)
                    O[i][j] = fmaf(a4[i], b4[j], O[i][j]);
        }
        __syncthreads();
    }

    // write y in (B, L, H*D) layout so the epilogue GEMM reads it row-major
    const int b = bh / H_, h = bh % H_;
#pragma unroll
    for (int i = 0; i < 4; i++) {
        const float inv = 1.f / lsum[i];
        const size_t row = (size_t)(b * L_ + q0 + tr * 4 + i) * E_ + h * 64 + tc * 4;
        float4 o;
        o.x = O[i][0] * inv; o.y = O[i][1] * inv;
        o.z = O[i][2] * inv; o.w = O[i][3] * inv;
        *(float4*)&g_y[row] = o;
    }
}

// ---------------- launch ---------------------------------------------------
extern "C" void kernel_launch(void* const* d_in, const int* in_sizes, int n_in,
                              void* d_out, int out_size)
{
    const float* xt  = (const float*)d_in[0];
    const float* xs  = (const float*)d_in[1];
    const float* Wt  = (const float*)d_in[2];
    const float* bt  = (const float*)d_in[3];
    const float* Ws  = (const float*)d_in[4];
    const float* bs  = (const float*)d_in[5];
    const float* Wc  = (const float*)d_in[6];
    const float* bc  = (const float*)d_in[7];
    const float* lts = (const float*)d_in[8];
    const float* lst = (const float*)d_in[9];
    const float* lss = (const float*)d_in[10];
    float* out = (float*)d_out;

    float *qkvt, *qsks, *y;
    cudaGetSymbolAddress((void**)&qkvt, g_qkvt);
    cudaGetSymbolAddress((void**)&qsks, g_qsks);
    cudaGetSymbolAddress((void**)&y,    g_y);

    const int ATTN_SMEM = 24576 * sizeof(float);   // 96 KB
    cudaFuncSetAttribute(attn_kernel,
                         cudaFuncAttributeMaxDynamicSharedMemorySize, ATTN_SMEM);

    // 1) xt @ Wt + bt -> qkvt (4096 x 3072)
    gemm_bias<<<dim3(3 * E_ / 128, BL_ / 128), 256>>>(xt, Wt, bt, qkvt, 3 * E_, E_);
    // 2) xs @ Ws + bs -> qsks (4096 x 2048)
    gemm_bias<<<dim3(2 * E_ / 128, BL_ / 128), 256>>>(xs, Ws, bs, qsks, 2 * E_, E_);
    // 3) pack Q'/K'/V
    pack_kernel<<<BL_, 256>>>(lts, lst, lss);
    // 4) attention
    attn_kernel<<<dim3(L_ / 64, BH_), 256, ATTN_SMEM>>>();
    // 5) y @ Wc + bc -> out (4096 x 1024)
    gemm_bias<<<dim3(E_ / 128, BL_ / 128), 256>>>(y, Wc, bc, out, E_, E_);
}

// round 2
// speedup vs baseline: 3.5910x; 3.5910x over previous
#include <cuda_runtime.h>
#include <cstdint>

#define B_ 2
#define L_ 2048
#define E_ 1024
#define H_ 16
#define D_ 64
#define BL_ (B_*L_)
#define BH_ (B_*H_)

// ---------------- scratch (device globals) ---------------------------------
__device__ float g_qkvt[(size_t)BL_ * 3*E_];
__device__ float g_qsks[(size_t)BL_ * 2*E_];
__device__ float g_Qp[(size_t)BH_ * L_ * 128];  // tf32-rounded, scaled
__device__ float g_Kp[(size_t)BH_ * L_ * 128];  // tf32-rounded
__device__ float g_Vp[(size_t)BH_ * L_ * 64];   // tf32-rounded
__device__ float g_y [(size_t)BL_ * E_];        // tf32-rounded attn out
__device__ float g_xtr[(size_t)BL_ * E_];
__device__ float g_xsr[(size_t)BL_ * E_];
__device__ float g_Wtr[(size_t)E_ * 3*E_];
__device__ float g_Wsr[(size_t)E_ * 2*E_];
__device__ float g_Wcr[(size_t)E_ * E_];

// ---------------- helpers ---------------------------------------------------
__device__ __forceinline__ uint32_t f2tf(float x){
    uint32_t r; asm("cvt.rna.tf32.f32 %0, %1;" : "=r"(r) : "f"(x)); return r;
}
__device__ __forceinline__ float f2tff(float x){ return __uint_as_float(f2tf(x)); }

__device__ __forceinline__ void mma_tf32(float c[4],
    uint32_t a0,uint32_t a1,uint32_t a2,uint32_t a3,uint32_t b0,uint32_t b1){
    asm volatile("mma.sync.aligned.m16n8k8.row.col.f32.tf32.tf32.f32 "
        "{%0,%1,%2,%3}, {%4,%5,%6,%7}, {%8,%9}, {%0,%1,%2,%3};"
        : "+f"(c[0]),"+f"(c[1]),"+f"(c[2]),"+f"(c[3])
        : "r"(a0),"r"(a1),"r"(a2),"r"(a3),"r"(b0),"r"(b1));
}
__device__ __forceinline__ void cp16(uint32_t dst, const void* src){
    asm volatile("cp.async.cg.shared.global [%0], [%1], 16;" :: "r"(dst), "l"(src));
}
__device__ __forceinline__ void cp_commit(){ asm volatile("cp.async.commit_group;"); }
template<int N> __device__ __forceinline__ void cp_wait(){
    asm volatile("cp.async.wait_group %0;" :: "n"(N));
}

// ---------------- tf32 rounding pass ----------------------------------------
__global__ __launch_bounds__(256) void round_tf32_kernel(
    const float* __restrict__ in, float* __restrict__ out, int n4)
{
    int i = blockIdx.x*blockDim.x + threadIdx.x;
    if (i < n4){
        float4 v = *(const float4*)(in + (size_t)i*4);
        v.x=f2tff(v.x); v.y=f2tff(v.y); v.z=f2tff(v.z); v.w=f2tff(v.w);
        *(float4*)(out + (size_t)i*4) = v;
    }
}

// ---------------- GEMM: C[M,N] = A[M,K] @ W[K,N] + bias (tf32 mma) ----------
// BM=128, BN=128, BK=32, 8 warps (2x4), warp tile 64x32, m16n8k8.
__global__ __launch_bounds__(256) void gemm_mma(
    const float* __restrict__ A, const float* __restrict__ W,
    const float* __restrict__ bias, float* __restrict__ C, int N, int K)
{
    extern __shared__ float smx[];
    const int ASZ = 128*36, BSZ = 32*136;
    float* As = smx;            // [2][128][36]
    float* Bs = smx + 2*ASZ;    // [2][32][136]
    const int tid = threadIdx.x, lane = tid & 31, warp = tid >> 5;
    const int wm = warp >> 2, wn = warp & 3, gid = lane >> 2, tig = lane & 3;
    const int bM = blockIdx.y * 128, bN = blockIdx.x * 128;

    const uint32_t sA = (uint32_t)__cvta_generic_to_shared(As);
    const uint32_t sB = (uint32_t)__cvta_generic_to_shared(Bs);

    float c[4][4][4];
#pragma unroll
    for (int i=0;i<4;i++)
#pragma unroll
        for (int j=0;j<4;j++)
#pragma unroll
            for (int r=0;r<4;r++) c[i][j][r]=0.f;

    const int niter = K >> 5;

    // prologue: tile 0 -> buf 0
    {
        const int k0 = 0;
#pragma unroll
        for (int i=0;i<4;i++){
            int ch = tid + i*256, row = ch>>3, kc = (ch&7)<<2;
            cp16(sA + (uint32_t)(row*36 + kc)*4, A + (size_t)(bM+row)*K + k0 + kc);
        }
#pragma unroll
        for (int i=0;i<4;i++){
            int ch = tid + i*256, row = ch>>5, nc = (ch&31)<<2;
            cp16(sB + (uint32_t)(row*136 + nc)*4, W + (size_t)(k0+row)*N + bN + nc);
        }
        cp_commit();
    }

    for (int it = 0; it < niter; it++){
        const int cur = it & 1;
        if (it + 1 < niter){
            const int k0 = (it+1)*32, buf = cur^1;
#pragma unroll
            for (int i=0;i<4;i++){
                int ch = tid + i*256, row = ch>>3, kc = (ch&7)<<2;
                cp16(sA + (uint32_t)(buf*ASZ + row*36 + kc)*4,
                     A + (size_t)(bM+row)*K + k0 + kc);
            }
#pragma unroll
            for (int i=0;i<4;i++){
                int ch = tid + i*256, row = ch>>5, nc = (ch&31)<<2;
                cp16(sB + (uint32_t)(buf*BSZ + row*136 + nc)*4,
                     W + (size_t)(k0+row)*N + bN + nc);
            }
            cp_commit();
            cp_wait<1>();
        } else {
            cp_wait<0>();
        }
        __syncthreads();

        const float* As_ = As + cur*ASZ;
        const float* Bs_ = Bs + cur*BSZ;
#pragma unroll
        for (int kk = 0; kk < 4; kk++){
            const int kb = kk*8;
            uint32_t a[4][4], b[4][2];
#pragma unroll
            for (int i=0;i<4;i++){
                const int r0 = wm*64 + i*16 + gid;
                a[i][0] = __float_as_uint(As_[(r0   )*36 + kb + tig    ]);
                a[i][1] = __float_as_uint(As_[(r0+8 )*36 + kb + tig    ]);
                a[i][2] = __float_as_uint(As_[(r0   )*36 + kb + tig + 4]);
                a[i][3] = __float_as_uint(As_[(r0+8 )*36 + kb + tig + 4]);
            }
#pragma unroll
            for (int j=0;j<4;j++){
                const int n0 = wn*32 + j*8 + gid;
                b[j][0] = __float_as_uint(Bs_[(kb + tig    )*136 + n0]);
                b[j][1] = __float_as_uint(Bs_[(kb + tig + 4)*136 + n0]);
            }
#pragma unroll
            for (int i=0;i<4;i++)
#pragma unroll
                for (int j=0;j<4;j++)
                    mma_tf32(c[i][j], a[i][0],a[i][1],a[i][2],a[i][3], b[j][0],b[j][1]);
        }
        __syncthreads();
    }

    // epilogue
#pragma unroll
    for (int i=0;i<4;i++){
        const int row = bM + wm*64 + i*16 + gid;
#pragma unroll
        for (int j=0;j<4;j++){
            const int col = bN + wn*32 + j*8 + tig*2;
            const float b0 = bias[col], b1 = bias[col+1];
            float2 v0 = { c[i][j][0] + b0, c[i][j][1] + b1 };
            float2 v1 = { c[i][j][2] + b0, c[i][j][3] + b1 };
            *(float2*)(C + (size_t)row    *N + col) = v0;
            *(float2*)(C + (size_t)(row+8)*N + col) = v1;
        }
    }
}

// ---------------- pack: build Q'(scaled), K', V; round to tf32 --------------
__global__ __launch_bounds__(256) void pack_kernel(
    const float* __restrict__ lam_ts, const float* __restrict__ lam_st,
    const float* __restrict__ lam_ss)
{
    const int bl = blockIdx.x;
    const int b = bl / L_, l = bl % L_;
    const int tid = threadIdx.x;
    const float lts = lam_ts[0], lst = lam_st[0], lss = lam_ss[0];
    const float* qkv = g_qkvt + (size_t)bl * 3*E_;
    const float* qk  = g_qsks + (size_t)bl * 2*E_;
    const float scale = 0.125f;

    for (int e = tid; e < H_*128; e += 256){
        const int h = e >> 7, d = e & 127;
        const size_t o = ((size_t)(b*H_ + h)*L_ + l)*128 + d;
        float qv, kv;
        if (d < 64){
            qv = qkv[h*64 + d];
            kv = qkv[E_ + h*64 + d] + lts * qk[E_ + h*64 + d];
        } else {
            const int dd = d - 64;
            qv = qk[h*64 + dd];
            kv = lst * qkv[E_ + h*64 + dd] + lss * qk[E_ + h*64 + dd];
        }
        g_Qp[o] = f2tff(qv * scale);
        g_Kp[o] = f2tff(kv);
    }
    for (int e = tid; e < H_*64; e += 256){
        const int h = e >> 6, d = e & 63;
        g_Vp[((size_t)(b*H_ + h)*L_ + l)*64 + d] = f2tff(qkv[2*E_ + h*64 + d]);
    }
}

// ---------------- flash attention (tf32 mma): BQ=128, BK=64, d=128 ----------
__global__ __launch_bounds__(256) void attn_mma()
{
    extern __shared__ float smx[];
    const int KSZ = 64*132, VSZ = 64*136;
    float* Ks = smx;                   // [2][64][132]
    float* Vs = smx + 2*KSZ;           // [2][64][136]
    float* Ps = smx + 2*KSZ + 2*VSZ;   // [128][68]
    const int tid = threadIdx.x, lane = tid & 31, warp = tid >> 5;
    const int gid = lane >> 2, tig = lane & 3;
    const int bh = blockIdx.y, q0 = blockIdx.x * 128;
    const int w16 = warp * 16;

    const float* Qg = g_Qp + (size_t)bh * L_ * 128;
    const float* Kg = g_Kp + (size_t)bh * L_ * 128;
    const float* Vg = g_Vp + (size_t)bh * L_ * 64;

    const uint32_t sK = (uint32_t)__cvta_generic_to_shared(Ks);
    const uint32_t sV = (uint32_t)__cvta_generic_to_shared(Vs);

    // Q fragments in registers (16 ksteps x 4 regs)
    uint32_t qa[16][4];
    {
        const float* qr0 = Qg + (size_t)(q0 + w16 + gid)*128;
        const float* qr1 = qr0 + 8*128;
#pragma unroll
        for (int kk=0;kk<16;kk++){
            qa[kk][0] = __float_as_uint(qr0[kk*8 + tig    ]);
            qa[kk][1] = __float_as_uint(qr1[kk*8 + tig    ]);
            qa[kk][2] = __float_as_uint(qr0[kk*8 + tig + 4]);
            qa[kk][3] = __float_as_uint(qr1[kk*8 + tig + 4]);
        }
    }

    float o[8][4];
#pragma unroll
    for (int j=0;j<8;j++){ o[j][0]=0.f; o[j][1]=0.f; o[j][2]=0.f; o[j][3]=0.f; }
    float mA = -1e30f, mB = -1e30f, lA = 0.f, lB = 0.f;

    // prologue prefetch tile 0
    {
        const int t = 0;
#pragma unroll
        for (int i=0;i<8;i++){
            int ch = tid + i*256, row = ch>>5, dc = (ch&31)<<2;
            cp16(sK + (uint32_t)(row*132 + dc)*4, Kg + (size_t)(t*64+row)*128 + dc);
        }
#pragma unroll
        for (int i=0;i<4;i++){
            int ch = tid + i*256, row = ch>>4, nc = (ch&15)<<2;
            cp16(sV + (uint32_t)(row*136 + nc)*4, Vg + (size_t)(t*64+row)*64 + nc);
        }
        cp_commit();
    }

    for (int t = 0; t < 32; t++){
        const int cur = t & 1;
        if (t < 31){
            const int tn = t+1, buf = cur^1;
#pragma unroll
            for (int i=0;i<8;i++){
                int ch = tid + i*256, row = ch>>5, dc = (ch&31)<<2;
                cp16(sK + (uint32_t)(buf*KSZ + row*132 + dc)*4,
                     Kg + (size_t)(tn*64+row)*128 + dc);
            }
#pragma unroll
            for (int i=0;i<4;i++){
                int ch = tid + i*256, row = ch>>4, nc = (ch&15)<<2;
                cp16(sV + (uint32_t)(buf*VSZ + row*136 + nc)*4,
                     Vg + (size_t)(tn*64+row)*64 + nc);
            }
            cp_commit();
            cp_wait<1>();
        } else {
            cp_wait<0>();
        }
        __syncthreads();

        const float* K_ = Ks + cur*KSZ;
        const float* V_ = Vs + cur*VSZ;

        // S = Q @ K^T   (warp: 16 q-rows x 64 keys)
        float s[8][4];
#pragma unroll
        for (int j=0;j<8;j++){ s[j][0]=0.f; s[j][1]=0.f; s[j][2]=0.f; s[j][3]=0.f; }
#pragma unroll
        for (int kk=0;kk<16;kk++){
            const int kb = kk*8;
#pragma unroll
            for (int j=0;j<8;j++){
                const int n0 = j*8 + gid;
                uint32_t b0 = __float_as_uint(K_[n0*132 + kb + tig    ]);
                uint32_t b1 = __float_as_uint(K_[n0*132 + kb + tig + 4]);
                mma_tf32(s[j], qa[kk][0],qa[kk][1],qa[kk][2],qa[kk][3], b0,b1);
            }
        }

        // online softmax (rows gid and gid+8 of warp tile; 4-lane reductions)
        float rmA = -1e30f, rmB = -1e30f;
#pragma unroll
        for (int j=0;j<8;j++){
            rmA = fmaxf(rmA, fmaxf(s[j][0], s[j][1]));
            rmB = fmaxf(rmB, fmaxf(s[j][2], s[j][3]));
        }
        rmA = fmaxf(rmA, __shfl_xor_sync(0xffffffffu, rmA, 1));
        rmA = fmaxf(rmA, __shfl_xor_sync(0xffffffffu, rmA, 2));
        rmB = fmaxf(rmB, __shfl_xor_sync(0xffffffffu, rmB, 1));
        rmB = fmaxf(rmB, __shfl_xor_sync(0xffffffffu, rmB, 2));
        const float nmA = fmaxf(mA, rmA), nmB = fmaxf(mB, rmB);
        const float aA = __expf(mA - nmA), aB = __expf(mB - nmB);
        mA = nmA; mB = nmB;
        float sumA = 0.f, sumB = 0.f;
#pragma unroll
        for (int j=0;j<8;j++){
            float p0 = __expf(s[j][0]-nmA), p1 = __expf(s[j][1]-nmA);
            float p2 = __expf(s[j][2]-nmB), p3 = __expf(s[j][3]-nmB);
            sumA += p0 + p1; sumB += p2 + p3;
            float2 vA = { f2tff(p0), f2tff(p1) };
            float2 vB = { f2tff(p2), f2tff(p3) };
            *(float2*)&Ps[(w16+gid  )*68 + j*8 + tig*2] = vA;
            *(float2*)&Ps[(w16+gid+8)*68 + j*8 + tig*2] = vB;
            o[j][0]*=aA; o[j][1]*=aA; o[j][2]*=aB; o[j][3]*=aB;
        }
        sumA += __shfl_xor_sync(0xffffffffu, sumA, 1);
        sumA += __shfl_xor_sync(0xffffffffu, sumA, 2);
        sumB += __shfl_xor_sync(0xffffffffu, sumB, 1);
        sumB += __shfl_xor_sync(0xffffffffu, sumB, 2);
        lA = lA*aA + sumA; lB = lB*aB + sumB;
        __syncthreads();

        // O += P @ V
#pragma unroll
        for (int kk=0;kk<8;kk++){
            const int kb = kk*8;
            uint32_t a0 = __float_as_uint(Ps[(w16+gid  )*68 + kb + tig    ]);
            uint32_t a1 = __float_as_uint(Ps[(w16+gid+8)*68 + kb + tig    ]);
            uint32_t a2 = __float_as_uint(Ps[(w16+gid  )*68 + kb + tig + 4]);
            uint32_t a3 = __float_as_uint(Ps[(w16+gid+8)*68 + kb + tig + 4]);
#pragma unroll
            for (int j=0;j<8;j++){
                const int n0 = j*8 + gid;
                uint32_t b0 = __float_as_uint(V_[(kb + tig    )*136 + n0]);
                uint32_t b1 = __float_as_uint(V_[(kb + tig + 4)*136 + n0]);
                mma_tf32(o[j], a0,a1,a2,a3, b0,b1);
            }
        }
        __syncthreads();
    }

    // epilogue: normalize, round to tf32 (input of final GEMM), write y
    const int b = bh / H_, h = bh % H_;
    const float iA = 1.f/lA, iB = 1.f/lB;
    const int rowA = b*L_ + q0 + w16 + gid;
#pragma unroll
    for (int j=0;j<8;j++){
        const int col = h*64 + j*8 + tig*2;
        float2 vA = { f2tff(o[j][0]*iA), f2tff(o[j][1]*iA) };
        float2 vB = { f2tff(o[j][2]*iB), f2tff(o[j][3]*iB) };
        *(float2*)&g_y[(size_t)rowA    *E_ + col] = vA;
        *(float2*)&g_y[(size_t)(rowA+8)*E_ + col] = vB;
    }
}

// ---------------- launch ----------------------------------------------------
extern "C" void kernel_launch(void* const* d_in, const int* in_sizes, int n_in,
                              void* d_out, int out_size)
{
    const float* xt  = (const float*)d_in[0];
    const float* xs  = (const float*)d_in[1];
    const float* Wt  = (const float*)d_in[2];
    const float* bt  = (const float*)d_in[3];
    const float* Ws  = (const float*)d_in[4];
    const float* bs  = (const float*)d_in[5];
    const float* Wc  = (const float*)d_in[6];
    const float* bc  = (const float*)d_in[7];
    const float* lts = (const float*)d_in[8];
    const float* lst = (const float*)d_in[9];
    const float* lss = (const float*)d_in[10];
    float* out = (float*)d_out;

    float *qkvt, *qsks, *y, *xtr, *xsr, *Wtr, *Wsr, *Wcr;
    cudaGetSymbolAddress((void**)&qkvt, g_qkvt);
    cudaGetSymbolAddress((void**)&qsks, g_qsks);
    cudaGetSymbolAddress((void**)&y,    g_y);
    cudaGetSymbolAddress((void**)&xtr,  g_xtr);
    cudaGetSymbolAddress((void**)&xsr,  g_xsr);
    cudaGetSymbolAddress((void**)&Wtr,  g_Wtr);
    cudaGetSymbolAddress((void**)&Wsr,  g_Wsr);
    cudaGetSymbolAddress((void**)&Wcr,  g_Wcr);

    const int GEMM_SMEM = (2*128*36 + 2*32*136) * 4;      // 71680 B
    const int ATTN_SMEM = (2*64*132 + 2*64*136 + 128*68) * 4; // 172032 B
    cudaFuncSetAttribute(gemm_mma,
        cudaFuncAttributeMaxDynamicSharedMemorySize, GEMM_SMEM);
    cudaFuncSetAttribute(attn_mma,
        cudaFuncAttributeMaxDynamicSharedMemorySize, ATTN_SMEM);

    // 0) round inputs to tf32 (unbiased rna)
    round_tf32_kernel<<<(BL_*E_/4 + 255)/256, 256>>>(xt, xtr, BL_*E_/4);
    round_tf32_kernel<<<(BL_*E_/4 + 255)/256, 256>>>(xs, xsr, BL_*E_/4);
    round_tf32_kernel<<<(E_*3*E_/4 + 255)/256, 256>>>(Wt, Wtr, E_*3*E_/4);
    round_tf32_kernel<<<(E_*2*E_/4 + 255)/256, 256>>>(Ws, Wsr, E_*2*E_/4);
    round_tf32_kernel<<<(E_*E_/4 + 255)/256, 256>>>(Wc, Wcr, E_*E_/4);

    // 1) xt @ Wt + bt
    gemm_mma<<<dim3(3*E_/128, BL_/128), 256, GEMM_SMEM>>>(xtr, Wtr, bt, qkvt, 3*E_, E_);
    // 2) xs @ Ws + bs
    gemm_mma<<<dim3(2*E_/128, BL_/128), 256, GEMM_SMEM>>>(xsr, Wsr, bs, qsks, 2*E_, E_);
    // 3) pack + round
    pack_kernel<<<BL_, 256>>>(lts, lst, lss);
    // 4) attention
    attn_mma<<<dim3(L_/128, BH_), 256, ATTN_SMEM>>>();
    // 5) y @ Wc + bc -> out
    gemm_mma<<<dim3(E_/128, BL_/128), 256, GEMM_SMEM>>>(y, Wcr, bc, out, E_, E_);
}

// round 6
// speedup vs baseline: 6.8370x; 1.9039x over previous
#include <cuda_runtime.h>
#include <cuda_fp16.h>
#include <cstdint>

#define B_ 2
#define L_ 2048
#define E_ 1024
#define H_ 16
#define D_ 64
#define BL_ (B_*L_)
#define BH_ (B_*H_)

// ---------------- scratch (device globals) ---------------------------------
__device__ float  g_qkvt[(size_t)BL_ * 3*E_];
__device__ float  g_qsks[(size_t)BL_ * 2*E_];
__device__ __half g_Qp[(size_t)BH_ * L_ * 128];
__device__ __half g_Kp[(size_t)BH_ * L_ * 128];
__device__ __half g_Vp[(size_t)BH_ * L_ * 64];
__device__ __half g_y [(size_t)BL_ * E_];
__device__ __half g_xth[(size_t)BL_ * E_];
__device__ __half g_xsh[(size_t)BL_ * E_];
__device__ __half g_Wth[(size_t)E_ * 3*E_];
__device__ __half g_Wsh[(size_t)E_ * 2*E_];
__device__ __half g_Wch[(size_t)E_ * E_];

// ---------------- helpers ----------------------------------------------------
union H2U { __half2 h; uint32_t u; };
__device__ __forceinline__ uint32_t h2u(__half2 v){ H2U x; x.h = v; return x.u; }

__device__ __forceinline__ void mma_f16(float c[4],
    uint32_t a0,uint32_t a1,uint32_t a2,uint32_t a3,uint32_t b0,uint32_t b1){
    asm volatile("mma.sync.aligned.m16n8k16.row.col.f32.f16.f16.f32 "
        "{%0,%1,%2,%3}, {%4,%5,%6,%7}, {%8,%9}, {%0,%1,%2,%3};"
        : "+f"(c[0]),"+f"(c[1]),"+f"(c[2]),"+f"(c[3])
        : "r"(a0),"r"(a1),"r"(a2),"r"(a3),"r"(b0),"r"(b1));
}
__device__ __forceinline__ void ldsm4(uint32_t& r0,uint32_t& r1,uint32_t& r2,uint32_t& r3,
                                      uint32_t addr){
    asm volatile("ldmatrix.sync.aligned.m8n8.x4.shared.b16 {%0,%1,%2,%3}, [%4];"
        : "=r"(r0),"=r"(r1),"=r"(r2),"=r"(r3) : "r"(addr));
}
__device__ __forceinline__ void ldsm4t(uint32_t& r0,uint32_t& r1,uint32_t& r2,uint32_t& r3,
                                       uint32_t addr){
    asm volatile("ldmatrix.sync.aligned.m8n8.x4.trans.shared.b16 {%0,%1,%2,%3}, [%4];"
        : "=r"(r0),"=r"(r1),"=r"(r2),"=r"(r3) : "r"(addr));
}
__device__ __forceinline__ void cp16(uint32_t dst, const void* src){
    asm volatile("cp.async.cg.shared.global [%0], [%1], 16;" :: "r"(dst), "l"(src));
}
__device__ __forceinline__ void cp_commit(){ asm volatile("cp.async.commit_group;"); }
template<int N> __device__ __forceinline__ void cp_wait(){
    asm volatile("cp.async.wait_group %0;" :: "n"(N));
}

// ---------------- fp32 -> fp16 conversion ------------------------------------
__global__ __launch_bounds__(256) void cvt_h_kernel(
    const float* __restrict__ in, __half* __restrict__ out, int n8)
{
    int i = blockIdx.x*blockDim.x + threadIdx.x;
    if (i < n8){
        float4 a = *(const float4*)(in + (size_t)i*8);
        float4 b = *(const float4*)(in + (size_t)i*8 + 4);
        __half2 h[4];
        h[0] = __floats2half2_rn(a.x, a.y);
        h[1] = __floats2half2_rn(a.z, a.w);
        h[2] = __floats2half2_rn(b.x, b.y);
        h[3] = __floats2half2_rn(b.z, b.w);
        *(float4*)(out + (size_t)i*8) = *(float4*)h;
    }
}

// ---------------- GEMM: C[M,N] = A[M,K]@W[K,N] + bias (fp16 mma, fp32 out) --
// BM=128, BN=128, BK=32(half), 8 warps (2x4), warp tile 64x32.
#define ASTR 40
#define BSTR 136
__global__ __launch_bounds__(256) void gemm_h(
    const __half* __restrict__ A, const __half* __restrict__ W,
    const float* __restrict__ bias, float* __restrict__ C, int N, int K)
{
    extern __shared__ __half smh[];
    const int ASZ = 128*ASTR, BSZ = 32*BSTR;
    __half* As = smh;
    __half* Bs = smh + 2*ASZ;
    const int tid = threadIdx.x, lane = tid & 31, warp = tid >> 5;
    const int wm = warp >> 2, wn = warp & 3, gid = lane >> 2, tig = lane & 3;
    const int bM = blockIdx.y * 128, bN = blockIdx.x * 128;
    const uint32_t sA = (uint32_t)__cvta_generic_to_shared(As);
    const uint32_t sB = (uint32_t)__cvta_generic_to_shared(Bs);

    float c[4][4][4];
#pragma unroll
    for (int i=0;i<4;i++)
#pragma unroll
        for (int j=0;j<4;j++)
#pragma unroll
            for (int r=0;r<4;r++) c[i][j][r]=0.f;

    const int niter = K >> 5;
    const int lrow = (lane & 7) + ((lane >> 3) & 1) * 8;
    const int lcol = (lane >> 4) * 8;

    // prologue tile 0
    {
#pragma unroll
        for (int i=0;i<2;i++){
            int ch = tid + i*256, row = ch>>2, colh = (ch&3)*8;
            cp16(sA + (uint32_t)(row*ASTR + colh)*2, A + (size_t)(bM+row)*K + colh);
        }
#pragma unroll
        for (int i=0;i<2;i++){
            int ch = tid + i*256, row = ch>>4, colh = (ch&15)*8;
            cp16(sB + (uint32_t)(row*BSTR + colh)*2, W + (size_t)row*N + bN + colh);
        }
        cp_commit();
    }

    for (int it = 0; it < niter; it++){
        const int cur = it & 1;
        if (it + 1 < niter){
            const int k0 = (it+1)*32, buf = cur^1;
#pragma unroll
            for (int i=0;i<2;i++){
                int ch = tid + i*256, row = ch>>2, colh = (ch&3)*8;
                cp16(sA + (uint32_t)(buf*ASZ + row*ASTR + colh)*2,
                     A + (size_t)(bM+row)*K + k0 + colh);
            }
#pragma unroll
            for (int i=0;i<2;i++){
                int ch = tid + i*256, row = ch>>4, colh = (ch&15)*8;
                cp16(sB + (uint32_t)(buf*BSZ + row*BSTR + colh)*2,
                     W + (size_t)(k0+row)*N + bN + colh);
            }
            cp_commit();
            cp_wait<1>();
        } else {
            cp_wait<0>();
        }
        __syncthreads();

        const uint32_t aBase = sA + (uint32_t)cur*ASZ*2;
        const uint32_t bBase = sB + (uint32_t)cur*BSZ*2;
#pragma unroll
        for (int kk = 0; kk < 2; kk++){
            const int kb = kk*16;
            uint32_t a[4][4], b[4][2];
#pragma unroll
            for (int i=0;i<4;i++){
                const int r = wm*64 + i*16 + lrow;
                ldsm4(a[i][0],a[i][1],a[i][2],a[i][3],
                      aBase + (uint32_t)(r*ASTR + kb + lcol)*2);
            }
#pragma unroll
            for (int jj=0;jj<2;jj++){
                const int krow = kb + lrow;
                const int nc = wn*32 + jj*16 + lcol;
                uint32_t r0,r1,r2,r3;
                ldsm4t(r0,r1,r2,r3, bBase + (uint32_t)(krow*BSTR + nc)*2);
                b[jj*2  ][0]=r0; b[jj*2  ][1]=r1;
                b[jj*2+1][0]=r2; b[jj*2+1][1]=r3;
            }
#pragma unroll
            for (int i=0;i<4;i++)
#pragma unroll
                for (int j=0;j<4;j++)
                    mma_f16(c[i][j], a[i][0],a[i][1],a[i][2],a[i][3], b[j][0],b[j][1]);
        }
        __syncthreads();
    }

#pragma unroll
    for (int i=0;i<4;i++){
        const int row = bM + wm*64 + i*16 + gid;
#pragma unroll
        for (int j=0;j<4;j++){
            const int col = bN + wn*32 + j*8 + tig*2;
            const float b0 = bias[col], b1 = bias[col+1];
            float2 v0 = { c[i][j][0] + b0, c[i][j][1] + b1 };
            float2 v1 = { c[i][j][2] + b0, c[i][j][3] + b1 };
            *(float2*)(C + (size_t)row    *N + col) = v0;
            *(float2*)(C + (size_t)(row+8)*N + col) = v1;
        }
    }
}

// ---------------- pack: Q'(scaled)/K'/V -> fp16 ------------------------------
__global__ __launch_bounds__(256) void pack_kernel(
    const float* __restrict__ lam_ts, const float* __restrict__ lam_st,
    const float* __restrict__ lam_ss)
{
    const int bl = blockIdx.x;
    const int b = bl / L_, l = bl % L_;
    const int tid = threadIdx.x;
    const float lts = lam_ts[0], lst = lam_st[0], lss = lam_ss[0];
    const float* qkv = g_qkvt + (size_t)bl * 3*E_;
    const float* qk  = g_qsks + (size_t)bl * 2*E_;
    const float scale = 0.125f;

    for (int e = tid; e < H_*128; e += 256){
        const int h = e >> 7, d = e & 127;
        const size_t o = ((size_t)(b*H_ + h)*L_ + l)*128 + d;
        float qv, kv;
        if (d < 64){
            qv = qkv[h*64 + d];
            kv = qkv[E_ + h*64 + d] + lts * qk[E_ + h*64 + d];
        } else {
            const int dd = d - 64;
            qv = qk[h*64 + dd];
            kv = lst * qkv[E_ + h*64 + dd] + lss * qk[E_ + h*64 + dd];
        }
        g_Qp[o] = __float2half_rn(qv * scale);
        g_Kp[o] = __float2half_rn(kv);
    }
    for (int e = tid; e < H_*64; e += 256){
        const int h = e >> 6, d = e & 63;
        g_Vp[((size_t)(b*H_ + h)*L_ + l)*64 + d] =
            __float2half_rn(qkv[2*E_ + h*64 + d]);
    }
}

// ---------------- flash attention (fp16 mma): BQ=128, BK=64, d=128 ----------
#define KSTR 136
#define VSTR 72
__global__ __launch_bounds__(256) void attn_h()
{
    extern __shared__ __half smh[];
    const int KSZ = 64*KSTR, VSZ = 64*VSTR;
    __half* Ks = smh;
    __half* Vs = smh + 2*KSZ;
    const int tid = threadIdx.x, lane = tid & 31, warp = tid >> 5;
    const int gid = lane >> 2, tig = lane & 3;
    const int bh = blockIdx.y, q0 = blockIdx.x * 128;
    const int w16 = warp * 16;
    const int lrow = (lane & 7) + ((lane >> 3) & 1) * 8;
    const int lcol = (lane >> 4) * 8;

    const __half* Qg = g_Qp + (size_t)bh * L_ * 128;
    const __half* Kg = g_Kp + (size_t)bh * L_ * 128;
    const __half* Vg = g_Vp + (size_t)bh * L_ * 64;
    const uint32_t sK = (uint32_t)__cvta_generic_to_shared(Ks);
    const uint32_t sV = (uint32_t)__cvta_generic_to_shared(Vs);

    // Q fragments in registers: 8 k16-steps x 4 regs
    uint32_t qa[8][4];
    {
        const __half* q0p = Qg + (size_t)(q0 + w16 + gid)*128;
        const __half* q1p = q0p + 8*128;
#pragma unroll
        for (int kk=0;kk<8;kk++){
            qa[kk][0] = *(const uint32_t*)(q0p + kk*16 + 2*tig);
            qa[kk][1] = *(const uint32_t*)(q1p + kk*16 + 2*tig);
            qa[kk][2] = *(const uint32_t*)(q0p + kk*16 + 8 + 2*tig);
            qa[kk][3] = *(const uint32_t*)(q1p + kk*16 + 8 + 2*tig);
        }
    }

    float o[8][4];
#pragma unroll
    for (int j=0;j<8;j++){ o[j][0]=0.f; o[j][1]=0.f; o[j][2]=0.f; o[j][3]=0.f; }
    float mA = -1e30f, mB = -1e30f, lA = 0.f, lB = 0.f;

    // prologue: tile 0
    {
#pragma unroll
        for (int i=0;i<4;i++){
            int ch = tid + i*256, row = ch>>4, colh = (ch&15)*8;
            cp16(sK + (uint32_t)(row*KSTR + colh)*2, Kg + (size_t)row*128 + colh);
        }
#pragma unroll
        for (int i=0;i<2;i++){
            int ch = tid + i*256, row = ch>>3, colh = (ch&7)*8;
            cp16(sV + (uint32_t)(row*VSTR + colh)*2, Vg + (size_t)row*64 + colh);
        }
        cp_commit();
    }

    for (int t = 0; t < 32; t++){
        const int cur = t & 1;
        if (t < 31){
            const int r0g = (t+1)*64, buf = cur^1;
#pragma unroll
            for (int i=0;i<4;i++){
                int ch = tid + i*256, row = ch>>4, colh = (ch&15)*8;
                cp16(sK + (uint32_t)(buf*KSZ + row*KSTR + colh)*2,
                     Kg + (size_t)(r0g+row)*128 + colh);
            }
#pragma unroll
            for (int i=0;i<2;i++){
                int ch = tid + i*256, row = ch>>3, colh = (ch&7)*8;
                cp16(sV + (uint32_t)(buf*VSZ + row*VSTR + colh)*2,
                     Vg + (size_t)(r0g+row)*64 + colh);
            }
            cp_commit();
            cp_wait<1>();
        } else {
            cp_wait<0>();
        }
        __syncthreads();

        const uint32_t kBase = sK + (uint32_t)cur*KSZ*2;
        const uint32_t vBase = sV + (uint32_t)cur*VSZ*2;

        // S = Q @ K^T
        float s[8][4];
#pragma unroll
        for (int j=0;j<8;j++){ s[j][0]=0.f; s[j][1]=0.f; s[j][2]=0.f; s[j][3]=0.f; }
        const int krow = (lane & 7) + (lane >> 4) * 8;
        const int kcol = ((lane >> 3) & 1) * 8;
#pragma unroll
        for (int kk=0;kk<8;kk++){
            const int kb = kk*16;
#pragma unroll
            for (int jj=0;jj<4;jj++){
                uint32_t b0,b1,b2,b3;
                ldsm4(b0,b1,b2,b3,
                    kBase + (uint32_t)((jj*16 + krow)*KSTR + kb + kcol)*2);
                mma_f16(s[jj*2  ], qa[kk][0],qa[kk][1],qa[kk][2],qa[kk][3], b0,b1);
                mma_f16(s[jj*2+1], qa[kk][0],qa[kk][1],qa[kk][2],qa[kk][3], b2,b3);
            }
        }

        // online softmax
        float rmA = -1e30f, rmB = -1e30f;
#pragma unroll
        for (int j=0;j<8;j++){
            rmA = fmaxf(rmA, fmaxf(s[j][0], s[j][1]));
            rmB = fmaxf(rmB, fmaxf(s[j][2], s[j][3]));
        }
        rmA = fmaxf(rmA, __shfl_xor_sync(0xffffffffu, rmA, 1));
        rmA = fmaxf(rmA, __shfl_xor_sync(0xffffffffu, rmA, 2));
        rmB = fmaxf(rmB, __shfl_xor_sync(0xffffffffu, rmB, 1));
        rmB = fmaxf(rmB, __shfl_xor_sync(0xffffffffu, rmB, 2));
        const float nmA = fmaxf(mA, rmA), nmB = fmaxf(mB, rmB);
        const float aA = __expf(mA - nmA), aB = __expf(mB - nmB);
        mA = nmA; mB = nmB;
        float sumA = 0.f, sumB = 0.f;
#pragma unroll
        for (int j=0;j<8;j++){
            s[j][0] = __expf(s[j][0]-nmA); s[j][1] = __expf(s[j][1]-nmA);
            s[j][2] = __expf(s[j][2]-nmB); s[j][3] = __expf(s[j][3]-nmB);
            sumA += s[j][0] + s[j][1];
            sumB += s[j][2] + s[j][3];
            o[j][0]*=aA; o[j][1]*=aA; o[j][2]*=aB; o[j][3]*=aB;
        }
        sumA += __shfl_xor_sync(0xffffffffu, sumA, 1);
        sumA += __shfl_xor_sync(0xffffffffu, sumA, 2);
        sumB += __shfl_xor_sync(0xffffffffu, sumB, 1);
        sumB += __shfl_xor_sync(0xffffffffu, sumB, 2);
        lA = lA*aA + sumA; lB = lB*aB + sumB;

        // P fragments (register repack: C-layout -> A-layout)
        uint32_t pa[4][4];
#pragma unroll
        for (int kk=0;kk<4;kk++){
            pa[kk][0] = h2u(__floats2half2_rn(s[2*kk  ][0], s[2*kk  ][1]));
            pa[kk][1] = h2u(__floats2half2_rn(s[2*kk  ][2], s[2*kk  ][3]));
            pa[kk][2] = h2u(__floats2half2_rn(s[2*kk+1][0], s[2*kk+1][1]));
            pa[kk][3] = h2u(__floats2half2_rn(s[2*kk+1][2], s[2*kk+1][3]));
        }

        // O += P @ V
#pragma unroll
        for (int kk=0;kk<4;kk++){
            const int kb = kk*16;
#pragma unroll
            for (int jj=0;jj<4;jj++){
                uint32_t b0,b1,b2,b3;
                ldsm4t(b0,b1,b2,b3,
                    vBase + (uint32_t)((kb + lrow)*VSTR + jj*16 + lcol)*2);
                mma_f16(o[jj*2  ], pa[kk][0],pa[kk][1],pa[kk][2],pa[kk][3], b0,b1);
                mma_f16(o[jj*2+1], pa[kk][0],pa[kk][1],pa[kk][2],pa[kk][3], b2,b3);
            }
        }
        __syncthreads();
    }

    // epilogue: normalize, write y as fp16 (input of final GEMM)
    const int b = bh / H_, h = bh % H_;
    const float iA = 1.f/lA, iB = 1.f/lB;
    const int rowA = b*L_ + q0 + w16 + gid;
#pragma unroll
    for (int j=0;j<8;j++){
        const int col = h*64 + j*8 + tig*2;
        __half2 vA = __floats2half2_rn(o[j][0]*iA, o[j][1]*iA);
        __half2 vB = __floats2half2_rn(o[j][2]*iB, o[j][3]*iB);
        *(__half2*)&g_y[(size_t)rowA    *E_ + col] = vA;
        *(__half2*)&g_y[(size_t)(rowA+8)*E_ + col] = vB;
    }
}

// ---------------- launch ----------------------------------------------------
extern "C" void kernel_launch(void* const* d_in, const int* in_sizes, int n_in,
                              void* d_out, int out_size)
{
    const float* xt  = (const float*)d_in[0];
    const float* xs  = (const float*)d_in[1];
    const float* Wt  = (const float*)d_in[2];
    const float* bt  = (const float*)d_in[3];
    const float* Ws  = (const float*)d_in[4];
    const float* bs  = (const float*)d_in[5];
    const float* Wc  = (const float*)d_in[6];
    const float* bc  = (const float*)d_in[7];
    const float* lts = (const float*)d_in[8];
    const float* lst = (const float*)d_in[9];
    const float* lss = (const float*)d_in[10];
    float* out = (float*)d_out;

    float *qkvt, *qsks;
    __half *y, *xth, *xsh, *Wth, *Wsh, *Wch;
    cudaGetSymbolAddress((void**)&qkvt, g_qkvt);
    cudaGetSymbolAddress((void**)&qsks, g_qsks);
    cudaGetSymbolAddress((void**)&y,    g_y);
    cudaGetSymbolAddress((void**)&xth,  g_xth);
    cudaGetSymbolAddress((void**)&xsh,  g_xsh);
    cudaGetSymbolAddress((void**)&Wth,  g_Wth);
    cudaGetSymbolAddress((void**)&Wsh,  g_Wsh);
    cudaGetSymbolAddress((void**)&Wch,  g_Wch);

    const int GEMM_SMEM = (2*128*ASTR + 2*32*BSTR) * 2;      // 37888 B
    const int ATTN_SMEM = (2*64*KSTR + 2*64*VSTR) * 2;       // 53248 B
    cudaFuncSetAttribute(gemm_h,
        cudaFuncAttributeMaxDynamicSharedMemorySize, GEMM_SMEM);
    cudaFuncSetAttribute(attn_h,
        cudaFuncAttributeMaxDynamicSharedMemorySize, ATTN_SMEM);

    // 0) fp32 -> fp16 conversions
    cvt_h_kernel<<<(BL_*E_/8 + 255)/256, 256>>>(xt, xth, BL_*E_/8);
    cvt_h_kernel<<<(BL_*E_/8 + 255)/256, 256>>>(xs, xsh, BL_*E_/8);
    cvt_h_kernel<<<(E_*3*E_/8 + 255)/256, 256>>>(Wt, Wth, E_*3*E_/8);
    cvt_h_kernel<<<(E_*2*E_/8 + 255)/256, 256>>>(Ws, Wsh, E_*2*E_/8);
    cvt_h_kernel<<<(E_*E_/8 + 255)/256, 256>>>(Wc, Wch, E_*E_/8);

    // 1) xt @ Wt + bt
    gemm_h<<<dim3(3*E_/128, BL_/128), 256, GEMM_SMEM>>>(xth, Wth, bt, qkvt, 3*E_, E_);
    // 2) xs @ Ws + bs
    gemm_h<<<dim3(2*E_/128, BL_/128), 256, GEMM_SMEM>>>(xsh, Wsh, bs, qsks, 2*E_, E_);
    // 3) pack -> fp16 Q'/K'/V
    pack_kernel<<<BL_, 256>>>(lts, lst, lss);
    // 4) attention
    attn_h<<<dim3(L_/128, BH_), 256, ATTN_SMEM>>>();
    // 5) y @ Wc + bc -> out
    gemm_h<<<dim3(E_/128, BL_/128), 256, GEMM_SMEM>>>(y, Wch, bc, out, E_, E_);
}

// round 8
// speedup vs baseline: 6.8603x; 1.0034x over previous
#include <cuda_runtime.h>
#include <cuda_fp16.h>
#include <cstdint>

#define B_ 2
#define L_ 2048
#define E_ 1024
#define H_ 16
#define D_ 64
#define BL_ (B_*L_)
#define BH_ (B_*H_)

// ---------------- scratch (device globals) ---------------------------------
__device__ __half g_Qp[(size_t)BH_ * L_ * 128];
__device__ __half g_Kp[(size_t)BH_ * L_ * 128];
__device__ __half g_Vp[(size_t)BH_ * L_ * 64];
__device__ __half g_y [(size_t)BL_ * E_];
__device__ __half g_xth[(size_t)BL_ * E_];
__device__ __half g_xsh[(size_t)BL_ * E_];
__device__ __half g_WtT[(size_t)E_ * 3*E_];
__device__ __half g_WsT[(size_t)E_ * 2*E_];
__device__ __half g_WcT[(size_t)E_ * E_];

// Q scale: 1/sqrt(64) * log2(e)  (softmax runs in base-2 domain)
#define QS 0.18033688011112042f

// ---------------- helpers ----------------------------------------------------
union H2U { __half2 h; uint32_t u; };
__device__ __forceinline__ uint32_t h2u(__half2 v){ H2U x; x.h = v; return x.u; }

__device__ __forceinline__ float ex2f(float x){
    float r; asm("ex2.approx.f32 %0, %1;" : "=f"(r) : "f"(x)); return r;
}
__device__ __forceinline__ void mma_f16(float c[4],
    uint32_t a0,uint32_t a1,uint32_t a2,uint32_t a3,uint32_t b0,uint32_t b1){
    asm volatile("mma.sync.aligned.m16n8k16.row.col.f32.f16.f16.f32 "
        "{%0,%1,%2,%3}, {%4,%5,%6,%7}, {%8,%9}, {%0,%1,%2,%3};"
        : "+f"(c[0]),"+f"(c[1]),"+f"(c[2]),"+f"(c[3])
        : "r"(a0),"r"(a1),"r"(a2),"r"(a3),"r"(b0),"r"(b1));
}
__device__ __forceinline__ void ldsm4(uint32_t& r0,uint32_t& r1,uint32_t& r2,uint32_t& r3,
                                      uint32_t addr){
    asm volatile("ldmatrix.sync.aligned.m8n8.x4.shared.b16 {%0,%1,%2,%3}, [%4];"
        : "=r"(r0),"=r"(r1),"=r"(r2),"=r"(r3) : "r"(addr));
}
__device__ __forceinline__ void ldsm4t(uint32_t& r0,uint32_t& r1,uint32_t& r2,uint32_t& r3,
                                       uint32_t addr){
    asm volatile("ldmatrix.sync.aligned.m8n8.x4.trans.shared.b16 {%0,%1,%2,%3}, [%4];"
        : "=r"(r0),"=r"(r1),"=r"(r2),"=r"(r3) : "r"(addr));
}
__device__ __forceinline__ void cp16(uint32_t dst, const void* src){
    asm volatile("cp.async.cg.shared.global [%0], [%1], 16;" :: "r"(dst), "l"(src));
}
__device__ __forceinline__ void cp_commit(){ asm volatile("cp.async.commit_group;"); }
template<int N> __device__ __forceinline__ void cp_wait(){
    asm volatile("cp.async.wait_group %0;" :: "n"(N));
}
__device__ __forceinline__ uint32_t s2u(const void* p){
    return (uint32_t)__cvta_generic_to_shared(p);
}

// ---------------- fp32 -> fp16 conversion ------------------------------------
__global__ __launch_bounds__(256) void cvt_h_kernel(
    const float* __restrict__ in, __half* __restrict__ out, int n8)
{
    int i = blockIdx.x*blockDim.x + threadIdx.x;
    if (i < n8){
        float4 a = *(const float4*)(in + (size_t)i*8);
        float4 b = *(const float4*)(in + (size_t)i*8 + 4);
        __half2 h[4];
        h[0] = __floats2half2_rn(a.x, a.y);
        h[1] = __floats2half2_rn(a.z, a.w);
        h[2] = __floats2half2_rn(b.x, b.y);
        h[3] = __floats2half2_rn(b.z, b.w);
        *(float4*)(out + (size_t)i*8) = *(float4*)h;
    }
}

// ---------------- fp32 [K,N] -> fp16 [N,K] transpose+convert -----------------
__global__ void cvtT_kernel(const float* __restrict__ in, __half* __restrict__ out,
                            int K, int N)
{
    __shared__ float tile[32][33];
    const int k0 = blockIdx.y * 32, n0 = blockIdx.x * 32;
    const int tx = threadIdx.x, ty = threadIdx.y;   // (32, 8)
#pragma unroll
    for (int i = 0; i < 4; i++)
        tile[ty + 8*i][tx] = in[(size_t)(k0 + ty + 8*i)*N + n0 + tx];
    __syncthreads();
#pragma unroll
    for (int i = 0; i < 4; i++)
        out[(size_t)(n0 + ty + 8*i)*K + k0 + tx] = __float2half_rn(tile[tx][ty + 8*i]);
}

// ---------------- GEMM core: fp16 mma, 3-stage, 1 sync/iter ------------------
// BM=128, BN=128, BK=32(half), 8 warps (2x4), warp tile 64x32.
// MODE 0: fp32 C + bias.  MODE 1: t-proj fused epilogue.  MODE 2: s-proj RMW.
#define ASTR 40
#define BSTR 136
#define GH_STAGE (128*ASTR + 32*BSTR)     // halfs per stage
template<int MODE>
__global__ __launch_bounds__(256) void gemm_h(
    const __half* __restrict__ A, const __half* __restrict__ W,
    const float* __restrict__ bias, float* __restrict__ C,
    const float* __restrict__ lamA, const float* __restrict__ lamB,
    int N, int K)
{
    extern __shared__ __half smh[];
    const int tid = threadIdx.x, lane = tid & 31, warp = tid >> 5;
    const int wm = warp >> 2, wn = warp & 3, gid = lane >> 2, tig = lane & 3;
    const int bM = blockIdx.y * 128, bN = blockIdx.x * 128;
    const uint32_t sbase = s2u(smh);

    float c[4][4][4];
#pragma unroll
    for (int i=0;i<4;i++)
#pragma unroll
        for (int j=0;j<4;j++)
#pragma unroll
            for (int r=0;r<4;r++) c[i][j][r]=0.f;

    const int niter = K >> 5;
    const int lrow = (lane & 7) + ((lane >> 3) & 1) * 8;
    const int lcol = (lane >> 4) * 8;

    auto load_chunk = [&](int ch_k, int s){
        const uint32_t aBuf = sbase + (uint32_t)(s*GH_STAGE)*2;
        const uint32_t bBuf = aBuf + (uint32_t)(128*ASTR)*2;
        const int k0 = ch_k * 32;
#pragma unroll
        for (int i=0;i<2;i++){
            int ch = tid + i*256, row = ch>>2, colh = (ch&3)*8;
            cp16(aBuf + (uint32_t)(row*ASTR + colh)*2,
                 A + (size_t)(bM+row)*K + k0 + colh);
        }
#pragma unroll
        for (int i=0;i<2;i++){
            int ch = tid + i*256, row = ch>>4, colh = (ch&15)*8;
            cp16(bBuf + (uint32_t)(row*BSTR + colh)*2,
                 W + (size_t)(k0+row)*N + bN + colh);
        }
        cp_commit();
    };

    load_chunk(0, 0);
    load_chunk(1, 1);

    for (int it = 0; it < niter; it++){
        if (it < niter-1) cp_wait<1>(); else cp_wait<0>();
        __syncthreads();
        if (it + 2 < niter) load_chunk(it+2, (it+2)%3);

        const int s = it % 3;
        const uint32_t aBase = sbase + (uint32_t)(s*GH_STAGE)*2;
        const uint32_t bBase = aBase + (uint32_t)(128*ASTR)*2;
#pragma unroll
        for (int kk = 0; kk < 2; kk++){
            const int kb = kk*16;
            uint32_t a[4][4], b[4][2];
#pragma unroll
            for (int i=0;i<4;i++){
                const int r = wm*64 + i*16 + lrow;
                ldsm4(a[i][0],a[i][1],a[i][2],a[i][3],
                      aBase + (uint32_t)(r*ASTR + kb + lcol)*2);
            }
#pragma unroll
            for (int jj=0;jj<2;jj++){
                const int krow = kb + lrow;
                const int nc = wn*32 + jj*16 + lcol;
                uint32_t r0,r1,r2,r3;
                ldsm4t(r0,r1,r2,r3, bBase + (uint32_t)(krow*BSTR + nc)*2);
                b[jj*2  ][0]=r0; b[jj*2  ][1]=r1;
                b[jj*2+1][0]=r2; b[jj*2+1][1]=r3;
            }
#pragma unroll
            for (int i=0;i<4;i++)
#pragma unroll
                for (int j=0;j<4;j++)
                    mma_f16(c[i][j], a[i][0],a[i][1],a[i][2],a[i][3], b[j][0],b[j][1]);
        }
    }

    // -------- epilogue --------
    const float lA = (MODE != 0) ? lamA[0] : 0.f;
    const float lB = (MODE == 2) ? lamB[0] : 0.f;
#pragma unroll
    for (int i=0;i<4;i++){
        const int row0 = bM + wm*64 + i*16 + gid;
#pragma unroll
        for (int j=0;j<4;j++){
            const int col = bN + wn*32 + j*8 + tig*2;
            const float b0 = bias[col], b1 = bias[col+1];
#pragma unroll
            for (int half_ = 0; half_ < 2; half_++){
                const int r = row0 + half_*8;
                const float v0 = c[i][j][half_*2  ] + b0;
                const float v1 = c[i][j][half_*2+1] + b1;
                if (MODE == 0){
                    *(float2*)(C + (size_t)r*N + col) = make_float2(v0, v1);
                } else {
                    const int bb = r >> 11, l = r & 2047;
                    if (MODE == 1){
                        if (col < 1024){
                            const int h = col>>6, d = col&63;
                            const size_t o = ((size_t)((bb<<4)+h)*L_ + l)*128 + d;
                            *(__half2*)&g_Qp[o] = __floats2half2_rn(v0*QS, v1*QS);
                        } else if (col < 2048){
                            const int cc = col-1024, h = cc>>6, d = cc&63;
                            const size_t o = ((size_t)((bb<<4)+h)*L_ + l)*128 + d;
                            *(__half2*)&g_Kp[o]    = __floats2half2_rn(v0, v1);
                            *(__half2*)&g_Kp[o+64] = __floats2half2_rn(lA*v0, lA*v1);
                        } else {
                            const int cc = col-2048, h = cc>>6, d = cc&63;
                            const size_t o = ((size_t)((bb<<4)+h)*L_ + l)*64 + d;
                            *(__half2*)&g_Vp[o] = __floats2half2_rn(v0, v1);
                        }
                    } else { // MODE 2
                        if (col < 1024){
                            const int h = col>>6, d = col&63;
                            const size_t o = ((size_t)((bb<<4)+h)*L_ + l)*128 + 64 + d;
                            *(__half2*)&g_Qp[o] = __floats2half2_rn(v0*QS, v1*QS);
                        } else {
                            const int cc = col-1024, h = cc>>6, d = cc&63;
                            const size_t o = ((size_t)((bb<<4)+h)*L_ + l)*128 + d;
                            float2 f0 = __half22float2(*(__half2*)&g_Kp[o]);
                            *(__half2*)&g_Kp[o] =
                                __floats2half2_rn(f0.x + lA*v0, f0.y + lA*v1);
                            float2 f1 = __half22float2(*(__half2*)&g_Kp[o+64]);
                            *(__half2*)&g_Kp[o+64] =
                                __floats2half2_rn(f1.x + lB*v0, f1.y + lB*v1);
                        }
                    }
                }
            }
        }
    }
}

// ---------------- flash attention: BQ=128, BK=64, 3-stage, 1 sync/tile ------
#define KSTR 136
#define VSTR 72
#define AT_STAGE (64*KSTR + 64*VSTR)      // halfs per stage
#define NT 32
__global__ __launch_bounds__(256) void attn_h()
{
    extern __shared__ __half smh[];
    const int tid = threadIdx.x, lane = tid & 31, warp = tid >> 5;
    const int gid = lane >> 2, tig = lane & 3;
    const int bh = blockIdx.y, q0 = blockIdx.x * 128;
    const int w16 = warp * 16;
    const int lrow = (lane & 7) + ((lane >> 3) & 1) * 8;
    const int lcol = (lane >> 4) * 8;

    const __half* Qg = g_Qp + (size_t)bh * L_ * 128;
    const __half* Kg = g_Kp + (size_t)bh * L_ * 128;
    const __half* Vg = g_Vp + (size_t)bh * L_ * 64;
    const uint32_t sbase = s2u(smh);

    uint32_t qa[8][4];
    {
        const __half* q0p = Qg + (size_t)(q0 + w16 + gid)*128;
        const __half* q1p = q0p + 8*128;
#pragma unroll
        for (int kk=0;kk<8;kk++){
            qa[kk][0] = *(const uint32_t*)(q0p + kk*16 + 2*tig);
            qa[kk][1] = *(const uint32_t*)(q1p + kk*16 + 2*tig);
            qa[kk][2] = *(const uint32_t*)(q0p + kk*16 + 8 + 2*tig);
            qa[kk][3] = *(const uint32_t*)(q1p + kk*16 + 8 + 2*tig);
        }
    }

    auto load_tile = [&](int t, int s){
        const uint32_t kBuf = sbase + (uint32_t)(s*AT_STAGE)*2;
        const uint32_t vBuf = kBuf + (uint32_t)(64*KSTR)*2;
        const int r0g = t*64;
#pragma unroll
        for (int i=0;i<4;i++){
            int ch = tid + i*256, row = ch>>4, colh = (ch&15)*8;
            cp16(kBuf + (uint32_t)(row*KSTR + colh)*2,
                 Kg + (size_t)(r0g+row)*128 + colh);
        }
#pragma unroll
        for (int i=0;i<2;i++){
            int ch = tid + i*256, row = ch>>3, colh = (ch&7)*8;
            cp16(vBuf + (uint32_t)(row*VSTR + colh)*2,
                 Vg + (size_t)(r0g+row)*64 + colh);
        }
        cp_commit();
    };

    float o[8][4];
#pragma unroll
    for (int j=0;j<8;j++){ o[j][0]=0.f; o[j][1]=0.f; o[j][2]=0.f; o[j][3]=0.f; }
    float mA = -1e30f, mB = -1e30f, lA = 0.f, lB = 0.f;

    load_tile(0, 0);
    load_tile(1, 1);

    for (int t = 0; t < NT; t++){
        if (t < NT-1) cp_wait<1>(); else cp_wait<0>();
        __syncthreads();
        if (t + 2 < NT) load_tile(t+2, (t+2)%3);

        const int s = t % 3;
        const uint32_t kBase = sbase + (uint32_t)(s*AT_STAGE)*2;
        const uint32_t vBase = kBase + (uint32_t)(64*KSTR)*2;

        // S = Q @ K^T
        float sc[8][4];
#pragma unroll
        for (int j=0;j<8;j++){ sc[j][0]=0.f; sc[j][1]=0.f; sc[j][2]=0.f; sc[j][3]=0.f; }
        const int krow = (lane & 7) + (lane >> 4) * 8;
        const int kcol = ((lane >> 3) & 1) * 8;
#pragma unroll
        for (int kk=0;kk<8;kk++){
            const int kb = kk*16;
#pragma unroll
            for (int jj=0;jj<4;jj++){
                uint32_t b0,b1,b2,b3;
                ldsm4(b0,b1,b2,b3,
                    kBase + (uint32_t)((jj*16 + krow)*KSTR + kb + kcol)*2);
                mma_f16(sc[jj*2  ], qa[kk][0],qa[kk][1],qa[kk][2],qa[kk][3], b0,b1);
                mma_f16(sc[jj*2+1], qa[kk][0],qa[kk][1],qa[kk][2],qa[kk][3], b2,b3);
            }
        }

        // online softmax (base-2 domain)
        float rmA = -1e30f, rmB = -1e30f;
#pragma unroll
        for (int j=0;j<8;j++){
            rmA = fmaxf(rmA, fmaxf(sc[j][0], sc[j][1]));
            rmB = fmaxf(rmB, fmaxf(sc[j][2], sc[j][3]));
        }
        rmA = fmaxf(rmA, __shfl_xor_sync(0xffffffffu, rmA, 1));
        rmA = fmaxf(rmA, __shfl_xor_sync(0xffffffffu, rmA, 2));
        rmB = fmaxf(rmB, __shfl_xor_sync(0xffffffffu, rmB, 1));
        rmB = fmaxf(rmB, __shfl_xor_sync(0xffffffffu, rmB, 2));
        const float nmA = fmaxf(mA, rmA), nmB = fmaxf(mB, rmB);
        const float aA = ex2f(mA - nmA), aB = ex2f(mB - nmB);
        mA = nmA; mB = nmB;
        float sumA = 0.f, sumB = 0.f;
#pragma unroll
        for (int j=0;j<8;j++){
            sc[j][0] = ex2f(sc[j][0]-nmA); sc[j][1] = ex2f(sc[j][1]-nmA);
            sc[j][2] = ex2f(sc[j][2]-nmB); sc[j][3] = ex2f(sc[j][3]-nmB);
            sumA += sc[j][0] + sc[j][1];
            sumB += sc[j][2] + sc[j][3];
            o[j][0]*=aA; o[j][1]*=aA; o[j][2]*=aB; o[j][3]*=aB;
        }
        sumA += __shfl_xor_sync(0xffffffffu, sumA, 1);
        sumA += __shfl_xor_sync(0xffffffffu, sumA, 2);
        sumB += __shfl_xor_sync(0xffffffffu, sumB, 1);
        sumB += __shfl_xor_sync(0xffffffffu, sumB, 2);
        lA = lA*aA + sumA; lB = lB*aB + sumB;

        // P fragments (register repack)
        uint32_t pa[4][4];
#pragma unroll
        for (int kk=0;kk<4;kk++){
            pa[kk][0] = h2u(__floats2half2_rn(sc[2*kk  ][0], sc[2*kk  ][1]));
            pa[kk][1] = h2u(__floats2half2_rn(sc[2*kk  ][2], sc[2*kk  ][3]));
            pa[kk][2] = h2u(__floats2half2_rn(sc[2*kk+1][0], sc[2*kk+1][1]));
            pa[kk][3] = h2u(__floats2half2_rn(sc[2*kk+1][2], sc[2*kk+1][3]));
        }

        // O += P @ V
#pragma unroll
        for (int kk=0;kk<4;kk++){
            const int kb = kk*16;
#pragma unroll
            for (int jj=0;jj<4;jj++){
                uint32_t b0,b1,b2,b3;
                ldsm4t(b0,b1,b2,b3,
                    vBase + (uint32_t)((kb + lrow)*VSTR + jj*16 + lcol)*2);
                mma_f16(o[jj*2  ], pa[kk][0],pa[kk][1],pa[kk][2],pa[kk][3], b0,b1);
                mma_f16(o[jj*2+1], pa[kk][0],pa[kk][1],pa[kk][2],pa[kk][3], b2,b3);
            }
        }
    }

    const int b = bh / H_, h = bh % H_;
    const float iA = 1.f/lA, iB = 1.f/lB;
    const int rowA = b*L_ + q0 + w16 + gid;
#pragma unroll
    for (int j=0;j<8;j++){
        const int col = h*64 + j*8 + tig*2;
        __half2 vA = __floats2half2_rn(o[j][0]*iA, o[j][1]*iA);
        __half2 vB = __floats2half2_rn(o[j][2]*iB, o[j][3]*iB);
        *(__half2*)&g_y[(size_t)rowA    *E_ + col] = vA;
        *(__half2*)&g_y[(size_t)(rowA+8)*E_ + col] = vB;
    }
}

// ---------------- launch ----------------------------------------------------
extern "C" void kernel_launch(void* const* d_in, const int* in_sizes, int n_in,
                              void* d_out, int out_size)
{
    const float* xt  = (const float*)d_in[0];
    const float* xs  = (const float*)d_in[1];
    const float* Wt  = (const float*)d_in[2];
    const float* bt  = (const float*)d_in[3];
    const float* Ws  = (const float*)d_in[4];
    const float* bs  = (const float*)d_in[5];
    const float* Wc  = (const float*)d_in[6];
    const float* bc  = (const float*)d_in[7];
    const float* lts = (const float*)d_in[8];
    const float* lst = (const float*)d_in[9];
    const float* lss = (const float*)d_in[10];
    float* out = (float*)d_out;

    __half *y, *xth, *xsh, *WtT, *WsT, *WcT;
    cudaGetSymbolAddress((void**)&y,    g_y);
    cudaGetSymbolAddress((void**)&xth,  g_xth);
    cudaGetSymbolAddress((void**)&xsh,  g_xsh);
    cudaGetSymbolAddress((void**)&WtT,  g_WtT);
    cudaGetSymbolAddress((void**)&WsT,  g_WsT);
    cudaGetSymbolAddress((void**)&WcT,  g_WcT);

    const int GEMM_SMEM = 3 * GH_STAGE * 2;    // 56832 B
    const int ATTN_SMEM = 3 * AT_STAGE * 2;    // 79872 B
    cudaFuncSetAttribute(gemm_h<0>,
        cudaFuncAttributeMaxDynamicSharedMemorySize, GEMM_SMEM);
    cudaFuncSetAttribute(gemm_h<1>,
        cudaFuncAttributeMaxDynamicSharedMemorySize, GEMM_SMEM);
    cudaFuncSetAttribute(gemm_h<2>,
        cudaFuncAttributeMaxDynamicSharedMemorySize, GEMM_SMEM);
    cudaFuncSetAttribute(attn_h,
        cudaFuncAttributeMaxDynamicSharedMemorySize, ATTN_SMEM);

    // 0) convert activations; transpose+convert weights (W stays [K,N] for B path)
    cvt_h_kernel<<<(BL_*E_/8 + 255)/256, 256>>>(xt, xth, BL_*E_/8);
    cvt_h_kernel<<<(BL_*E_/8 + 255)/256, 256>>>(xs, xsh, BL_*E_/8);
    cvt_h_kernel<<<(E_*3*E_/8 + 255)/256, 256>>>(Wt, WtT, E_*3*E_/8);
    cvt_h_kernel<<<(E_*2*E_/8 + 255)/256, 256>>>(Ws, WsT, E_*2*E_/8);
    cvt_h_kernel<<<(E_*E_/8 + 255)/256, 256>>>(Wc, WcT, E_*E_/8);

    // 1) t-proj: xt @ Wt + bt  -> fused pack (Q left, K' both halves, V)
    gemm_h<1><<<dim3(3*E_/128, BL_/128), 256, GEMM_SMEM>>>(
        xth, WtT, bt, nullptr, lst, nullptr, 3*E_, E_);
    // 2) s-proj: xs @ Ws + bs  -> fused pack (Q right, K' RMW)
    gemm_h<2><<<dim3(2*E_/128, BL_/128), 256, GEMM_SMEM>>>(
        xsh, WsT, bs, nullptr, lts, lss, 2*E_, E_);
    // 3) attention
    attn_h<<<dim3(L_/128, BH_), 256, ATTN_SMEM>>>();
    // 4) y @ Wc + bc -> out
    gemm_h<0><<<dim3(E_/128, BL_/128), 256, GEMM_SMEM>>>(
        y, WcT, bc, out, nullptr, nullptr, E_, E_);
}

// round 9
// speedup vs baseline: 7.4682x; 1.0886x over previous
#include <cuda_runtime.h>
#include <cuda_fp16.h>
#include <cstdint>

#define B_ 2
#define L_ 2048
#define E_ 1024
#define H_ 16
#define D_ 64
#define BL_ (B_*L_)
#define BH_ (B_*H_)

// ---------------- scratch (device globals) ---------------------------------
__device__ __half g_Qp[(size_t)BH_ * L_ * 128];
__device__ __half g_Kp[(size_t)BH_ * L_ * 128];
__device__ __half g_Vp[(size_t)BH_ * L_ * 64];
__device__ __half g_y [(size_t)BL_ * E_];
__device__ __half g_xth[(size_t)BL_ * E_];
__device__ __half g_xsh[(size_t)BL_ * E_];
__device__ __half g_WtT[(size_t)E_ * 3*E_];
__device__ __half g_WsT[(size_t)E_ * 2*E_];
__device__ __half g_WcT[(size_t)E_ * E_];

// Q scale: 1/sqrt(64) * log2(e)  (softmax runs in base-2 domain)
#define QS 0.18033688011112042f

// ---------------- helpers ----------------------------------------------------
union H2U { __half2 h; uint32_t u; };
__device__ __forceinline__ uint32_t h2u(__half2 v){ H2U x; x.h = v; return x.u; }

__device__ __forceinline__ float ex2f(float x){
    float r; asm("ex2.approx.f32 %0, %1;" : "=f"(r) : "f"(x)); return r;
}
__device__ __forceinline__ void mma_f16(float c[4],
    uint32_t a0,uint32_t a1,uint32_t a2,uint32_t a3,uint32_t b0,uint32_t b1){
    asm volatile("mma.sync.aligned.m16n8k16.row.col.f32.f16.f16.f32 "
        "{%0,%1,%2,%3}, {%4,%5,%6,%7}, {%8,%9}, {%0,%1,%2,%3};"
        : "+f"(c[0]),"+f"(c[1]),"+f"(c[2]),"+f"(c[3])
        : "r"(a0),"r"(a1),"r"(a2),"r"(a3),"r"(b0),"r"(b1));
}
__device__ __forceinline__ void ldsm4(uint32_t& r0,uint32_t& r1,uint32_t& r2,uint32_t& r3,
                                      uint32_t addr){
    asm volatile("ldmatrix.sync.aligned.m8n8.x4.shared.b16 {%0,%1,%2,%3}, [%4];"
        : "=r"(r0),"=r"(r1),"=r"(r2),"=r"(r3) : "r"(addr));
}
__device__ __forceinline__ void ldsm4t(uint32_t& r0,uint32_t& r1,uint32_t& r2,uint32_t& r3,
                                       uint32_t addr){
    asm volatile("ldmatrix.sync.aligned.m8n8.x4.trans.shared.b16 {%0,%1,%2,%3}, [%4];"
        : "=r"(r0),"=r"(r1),"=r"(r2),"=r"(r3) : "r"(addr));
}
__device__ __forceinline__ void cp16(uint32_t dst, const void* src){
    asm volatile("cp.async.cg.shared.global [%0], [%1], 16;" :: "r"(dst), "l"(src));
}
__device__ __forceinline__ void cp_commit(){ asm volatile("cp.async.commit_group;"); }
template<int N> __device__ __forceinline__ void cp_wait(){
    asm volatile("cp.async.wait_group %0;" :: "n"(N));
}
__device__ __forceinline__ uint32_t s2u(const void* p){
    return (uint32_t)__cvta_generic_to_shared(p);
}

// ---------------- fp32 -> fp16 conversion ------------------------------------
__global__ __launch_bounds__(256) void cvt_h_kernel(
    const float* __restrict__ in, __half* __restrict__ out, int n8)
{
    int i = blockIdx.x*blockDim.x + threadIdx.x;
    if (i < n8){
        float4 a = *(const float4*)(in + (size_t)i*8);
        float4 b = *(const float4*)(in + (size_t)i*8 + 4);
        __half2 h[4];
        h[0] = __floats2half2_rn(a.x, a.y);
        h[1] = __floats2half2_rn(a.z, a.w);
        h[2] = __floats2half2_rn(b.x, b.y);
        h[3] = __floats2half2_rn(b.z, b.w);
        *(float4*)(out + (size_t)i*8) = *(float4*)h;
    }
}

// ---------------- GEMM core: fp16 mma, 3-stage, 1 sync/iter ------------------
// BM=128, BN=128, BK=32(half), 8 warps (2x4), warp tile 64x32.
// MODE 0: fp32 C + bias.  MODE 1: t-proj fused epilogue.  MODE 2: s-proj RMW.
#define ASTR 40
#define BSTR 136
#define GH_STAGE (128*ASTR + 32*BSTR)     // halfs per stage
template<int MODE>
__global__ __launch_bounds__(256, 2) void gemm_h(
    const __half* __restrict__ A, const __half* __restrict__ W,
    const float* __restrict__ bias, float* __restrict__ C,
    const float* __restrict__ lamA, const float* __restrict__ lamB,
    int N, int K)
{
    extern __shared__ __half smh[];
    const int tid = threadIdx.x, lane = tid & 31, warp = tid >> 5;
    const int wm = warp >> 2, wn = warp & 3, gid = lane >> 2, tig = lane & 3;
    const int bM = blockIdx.y * 128, bN = blockIdx.x * 128;
    const uint32_t sbase = s2u(smh);

    float c[4][4][4];
#pragma unroll
    for (int i=0;i<4;i++)
#pragma unroll
        for (int j=0;j<4;j++)
#pragma unroll
            for (int r=0;r<4;r++) c[i][j][r]=0.f;

    const int niter = K >> 5;
    const int lrow = (lane & 7) + ((lane >> 3) & 1) * 8;
    const int lcol = (lane >> 4) * 8;

    auto load_chunk = [&](int ch_k, int s){
        const uint32_t aBuf = sbase + (uint32_t)(s*GH_STAGE)*2;
        const uint32_t bBuf = aBuf + (uint32_t)(128*ASTR)*2;
        const int k0 = ch_k * 32;
#pragma unroll
        for (int i=0;i<2;i++){
            int ch = tid + i*256, row = ch>>2, colh = (ch&3)*8;
            cp16(aBuf + (uint32_t)(row*ASTR + colh)*2,
                 A + (size_t)(bM+row)*K + k0 + colh);
        }
#pragma unroll
        for (int i=0;i<2;i++){
            int ch = tid + i*256, row = ch>>4, colh = (ch&15)*8;
            cp16(bBuf + (uint32_t)(row*BSTR + colh)*2,
                 W + (size_t)(k0+row)*N + bN + colh);
        }
        cp_commit();
    };

    load_chunk(0, 0);
    load_chunk(1, 1);

    for (int it = 0; it < niter; it++){
        if (it < niter-1) cp_wait<1>(); else cp_wait<0>();
        __syncthreads();
        if (it + 2 < niter) load_chunk(it+2, (it+2)%3);

        const int s = it % 3;
        const uint32_t aBase = sbase + (uint32_t)(s*GH_STAGE)*2;
        const uint32_t bBase = aBase + (uint32_t)(128*ASTR)*2;
#pragma unroll
        for (int kk = 0; kk < 2; kk++){
            const int kb = kk*16;
            uint32_t a[4][4], b[4][2];
#pragma unroll
            for (int i=0;i<4;i++){
                const int r = wm*64 + i*16 + lrow;
                ldsm4(a[i][0],a[i][1],a[i][2],a[i][3],
                      aBase + (uint32_t)(r*ASTR + kb + lcol)*2);
            }
#pragma unroll
            for (int jj=0;jj<2;jj++){
                const int krow = kb + lrow;
                const int nc = wn*32 + jj*16 + lcol;
                uint32_t r0,r1,r2,r3;
                ldsm4t(r0,r1,r2,r3, bBase + (uint32_t)(krow*BSTR + nc)*2);
                b[jj*2  ][0]=r0; b[jj*2  ][1]=r1;
                b[jj*2+1][0]=r2; b[jj*2+1][1]=r3;
            }
#pragma unroll
            for (int i=0;i<4;i++)
#pragma unroll
                for (int j=0;j<4;j++)
                    mma_f16(c[i][j], a[i][0],a[i][1],a[i][2],a[i][3], b[j][0],b[j][1]);
        }
    }

    // -------- epilogue --------
    const float lA = (MODE != 0) ? lamA[0] : 0.f;
    const float lB = (MODE == 2) ? lamB[0] : 0.f;
#pragma unroll
    for (int i=0;i<4;i++){
        const int row0 = bM + wm*64 + i*16 + gid;
#pragma unroll
        for (int j=0;j<4;j++){
            const int col = bN + wn*32 + j*8 + tig*2;
            const float b0 = bias[col], b1 = bias[col+1];
#pragma unroll
            for (int half_ = 0; half_ < 2; half_++){
                const int r = row0 + half_*8;
                const float v0 = c[i][j][half_*2  ] + b0;
                const float v1 = c[i][j][half_*2+1] + b1;
                if (MODE == 0){
                    *(float2*)(C + (size_t)r*N + col) = make_float2(v0, v1);
                } else {
                    const int bb = r >> 11, l = r & 2047;
                    if (MODE == 1){
                        if (col < 1024){
                            const int h = col>>6, d = col&63;
                            const size_t o = ((size_t)((bb<<4)+h)*L_ + l)*128 + d;
                            *(__half2*)&g_Qp[o] = __floats2half2_rn(v0*QS, v1*QS);
                        } else if (col < 2048){
                            const int cc = col-1024, h = cc>>6, d = cc&63;
                            const size_t o = ((size_t)((bb<<4)+h)*L_ + l)*128 + d;
                            *(__half2*)&g_Kp[o]    = __floats2half2_rn(v0, v1);
                            *(__half2*)&g_Kp[o+64] = __floats2half2_rn(lA*v0, lA*v1);
                        } else {
                            const int cc = col-2048, h = cc>>6, d = cc&63;
                            const size_t o = ((size_t)((bb<<4)+h)*L_ + l)*64 + d;
                            *(__half2*)&g_Vp[o] = __floats2half2_rn(v0, v1);
                        }
                    } else { // MODE 2
                        if (col < 1024){
                            const int h = col>>6, d = col&63;
                            const size_t o = ((size_t)((bb<<4)+h)*L_ + l)*128 + 64 + d;
                            *(__half2*)&g_Qp[o] = __floats2half2_rn(v0*QS, v1*QS);
                        } else {
                            const int cc = col-1024, h = cc>>6, d = cc&63;
                            const size_t o = ((size_t)((bb<<4)+h)*L_ + l)*128 + d;
                            float2 f0 = __half22float2(*(__half2*)&g_Kp[o]);
                            *(__half2*)&g_Kp[o] =
                                __floats2half2_rn(f0.x + lA*v0, f0.y + lA*v1);
                            float2 f1 = __half22float2(*(__half2*)&g_Kp[o+64]);
                            *(__half2*)&g_Kp[o+64] =
                                __floats2half2_rn(f1.x + lB*v0, f1.y + lB*v1);
                        }
                    }
                }
            }
        }
    }
}

// ---------------- flash attention: BQ=128, BK=64, 3-stage, 1 sync/tile ------
#define KSTR 136
#define VSTR 72
#define AT_STAGE (64*KSTR + 64*VSTR)      // halfs per stage
#define NT 32
__global__ __launch_bounds__(256, 2) void attn_h()
{
    extern __shared__ __half smh[];
    const int tid = threadIdx.x, lane = tid & 31, warp = tid >> 5;
    const int gid = lane >> 2, tig = lane & 3;
    const int bh = blockIdx.y, q0 = blockIdx.x * 128;
    const int w16 = warp * 16;
    const int lrow = (lane & 7) + ((lane >> 3) & 1) * 8;
    const int lcol = (lane >> 4) * 8;

    const __half* Qg = g_Qp + (size_t)bh * L_ * 128;
    const __half* Kg = g_Kp + (size_t)bh * L_ * 128;
    const __half* Vg = g_Vp + (size_t)bh * L_ * 64;
    const uint32_t sbase = s2u(smh);

    uint32_t qa[8][4];
    {
        const __half* q0p = Qg + (size_t)(q0 + w16 + gid)*128;
        const __half* q1p = q0p + 8*128;
#pragma unroll
        for (int kk=0;kk<8;kk++){
            qa[kk][0] = *(const uint32_t*)(q0p + kk*16 + 2*tig);
            qa[kk][1] = *(const uint32_t*)(q1p + kk*16 + 2*tig);
            qa[kk][2] = *(const uint32_t*)(q0p + kk*16 + 8 + 2*tig);
            qa[kk][3] = *(const uint32_t*)(q1p + kk*16 + 8 + 2*tig);
        }
    }

    auto load_tile = [&](int t, int s){
        const uint32_t kBuf = sbase + (uint32_t)(s*AT_STAGE)*2;
        const uint32_t vBuf = kBuf + (uint32_t)(64*KSTR)*2;
        const int r0g = t*64;
#pragma unroll
        for (int i=0;i<4;i++){
            int ch = tid + i*256, row = ch>>4, colh = (ch&15)*8;
            cp16(kBuf + (uint32_t)(row*KSTR + colh)*2,
                 Kg + (size_t)(r0g+row)*128 + colh);
        }
#pragma unroll
        for (int i=0;i<2;i++){
            int ch = tid + i*256, row = ch>>3, colh = (ch&7)*8;
            cp16(vBuf + (uint32_t)(row*VSTR + colh)*2,
                 Vg + (size_t)(r0g+row)*64 + colh);
        }
        cp_commit();
    };

    float o[8][4];
#pragma unroll
    for (int j=0;j<8;j++){ o[j][0]=0.f; o[j][1]=0.f; o[j][2]=0.f; o[j][3]=0.f; }
    float mA = -1e30f, mB = -1e30f, lA = 0.f, lB = 0.f;

    load_tile(0, 0);
    load_tile(1, 1);

    for (int t = 0; t < NT; t++){
        if (t < NT-1) cp_wait<1>(); else cp_wait<0>();
        __syncthreads();
        if (t + 2 < NT) load_tile(t+2, (t+2)%3);

        const int s = t % 3;
        const uint32_t kBase = sbase + (uint32_t)(s*AT_STAGE)*2;
        const uint32_t vBase = kBase + (uint32_t)(64*KSTR)*2;

        // S = Q @ K^T
        float sc[8][4];
#pragma unroll
        for (int j=0;j<8;j++){ sc[j][0]=0.f; sc[j][1]=0.f; sc[j][2]=0.f; sc[j][3]=0.f; }
        const int krow = (lane & 7) + (lane >> 4) * 8;
        const int kcol = ((lane >> 3) & 1) * 8;
#pragma unroll
        for (int kk=0;kk<8;kk++){
            const int kb = kk*16;
#pragma unroll
            for (int jj=0;jj<4;jj++){
                uint32_t b0,b1,b2,b3;
                ldsm4(b0,b1,b2,b3,
                    kBase + (uint32_t)((jj*16 + krow)*KSTR + kb + kcol)*2);
                mma_f16(sc[jj*2  ], qa[kk][0],qa[kk][1],qa[kk][2],qa[kk][3], b0,b1);
                mma_f16(sc[jj*2+1], qa[kk][0],qa[kk][1],qa[kk][2],qa[kk][3], b2,b3);
            }
        }

        // online softmax (base-2 domain)
        float rmA = -1e30f, rmB = -1e30f;
#pragma unroll
        for (int j=0;j<8;j++){
            rmA = fmaxf(rmA, fmaxf(sc[j][0], sc[j][1]));
            rmB = fmaxf(rmB, fmaxf(sc[j][2], sc[j][3]));
        }
        rmA = fmaxf(rmA, __shfl_xor_sync(0xffffffffu, rmA, 1));
        rmA = fmaxf(rmA, __shfl_xor_sync(0xffffffffu, rmA, 2));
        rmB = fmaxf(rmB, __shfl_xor_sync(0xffffffffu, rmB, 1));
        rmB = fmaxf(rmB, __shfl_xor_sync(0xffffffffu, rmB, 2));
        const float nmA = fmaxf(mA, rmA), nmB = fmaxf(mB, rmB);
        const float aA = ex2f(mA - nmA), aB = ex2f(mB - nmB);
        mA = nmA; mB = nmB;
        float sumA = 0.f, sumB = 0.f;
#pragma unroll
        for (int j=0;j<8;j++){
            sc[j][0] = ex2f(sc[j][0]-nmA); sc[j][1] = ex2f(sc[j][1]-nmA);
            sc[j][2] = ex2f(sc[j][2]-nmB); sc[j][3] = ex2f(sc[j][3]-nmB);
            sumA += sc[j][0] + sc[j][1];
            sumB += sc[j][2] + sc[j][3];
            o[j][0]*=aA; o[j][1]*=aA; o[j][2]*=aB; o[j][3]*=aB;
        }
        sumA += __shfl_xor_sync(0xffffffffu, sumA, 1);
        sumA += __shfl_xor_sync(0xffffffffu, sumA, 2);
        sumB += __shfl_xor_sync(0xffffffffu, sumB, 1);
        sumB += __shfl_xor_sync(0xffffffffu, sumB, 2);
        lA = lA*aA + sumA; lB = lB*aB + sumB;

        // P fragments (register repack)
        uint32_t pa[4][4];
#pragma unroll
        for (int kk=0;kk<4;kk++){
            pa[kk][0] = h2u(__floats2half2_rn(sc[2*kk  ][0], sc[2*kk  ][1]));
            pa[kk][1] = h2u(__floats2half2_rn(sc[2*kk  ][2], sc[2*kk  ][3]));
            pa[kk][2] = h2u(__floats2half2_rn(sc[2*kk+1][0], sc[2*kk+1][1]));
            pa[kk][3] = h2u(__floats2half2_rn(sc[2*kk+1][2], sc[2*kk+1][3]));
        }

        // O += P @ V
#pragma unroll
        for (int kk=0;kk<4;kk++){
            const int kb = kk*16;
#pragma unroll
            for (int jj=0;jj<4;jj++){
                uint32_t b0,b1,b2,b3;
                ldsm4t(b0,b1,b2,b3,
                    vBase + (uint32_t)((kb + lrow)*VSTR + jj*16 + lcol)*2);
                mma_f16(o[jj*2  ], pa[kk][0],pa[kk][1],pa[kk][2],pa[kk][3], b0,b1);
                mma_f16(o[jj*2+1], pa[kk][0],pa[kk][1],pa[kk][2],pa[kk][3], b2,b3);
            }
        }
    }

    const int b = bh / H_, h = bh % H_;
    const float iA = 1.f/lA, iB = 1.f/lB;
    const int rowA = b*L_ + q0 + w16 + gid;
#pragma unroll
    for (int j=0;j<8;j++){
        const int col = h*64 + j*8 + tig*2;
        __half2 vA = __floats2half2_rn(o[j][0]*iA, o[j][1]*iA);
        __half2 vB = __floats2half2_rn(o[j][2]*iB, o[j][3]*iB);
        *(__half2*)&g_y[(size_t)rowA    *E_ + col] = vA;
        *(__half2*)&g_y[(size_t)(rowA+8)*E_ + col] = vB;
    }
}

// ---------------- launch ----------------------------------------------------
extern "C" void kernel_launch(void* const* d_in, const int* in_sizes, int n_in,
                              void* d_out, int out_size)
{
    const float* xt  = (const float*)d_in[0];
    const float* xs  = (const float*)d_in[1];
    const float* Wt  = (const float*)d_in[2];
    const float* bt  = (const float*)d_in[3];
    const float* Ws  = (const float*)d_in[4];
    const float* bs  = (const float*)d_in[5];
    const float* Wc  = (const float*)d_in[6];
    const float* bc  = (const float*)d_in[7];
    const float* lts = (const float*)d_in[8];
    const float* lst = (const float*)d_in[9];
    const float* lss = (const float*)d_in[10];
    float* out = (float*)d_out;

    __half *y, *xth, *xsh, *WtT, *WsT, *WcT;
    cudaGetSymbolAddress((void**)&y,    g_y);
    cudaGetSymbolAddress((void**)&xth,  g_xth);
    cudaGetSymbolAddress((void**)&xsh,  g_xsh);
    cudaGetSymbolAddress((void**)&WtT,  g_WtT);
    cudaGetSymbolAddress((void**)&WsT,  g_WsT);
    cudaGetSymbolAddress((void**)&WcT,  g_WcT);

    const int GEMM_SMEM = 3 * GH_STAGE * 2;    // 56832 B
    const int ATTN_SMEM = 3 * AT_STAGE * 2;    // 79872 B
    cudaFuncSetAttribute(gemm_h<0>,
        cudaFuncAttributeMaxDynamicSharedMemorySize, GEMM_SMEM);
    cudaFuncSetAttribute(gemm_h<1>,
        cudaFuncAttributeMaxDynamicSharedMemorySize, GEMM_SMEM);
    cudaFuncSetAttribute(gemm_h<2>,
        cudaFuncAttributeMaxDynamicSharedMemorySize, GEMM_SMEM);
    cudaFuncSetAttribute(attn_h,
        cudaFuncAttributeMaxDynamicSharedMemorySize, ATTN_SMEM);

    // ---- fork side stream for independent s/c-path conversions --------------
    cudaStream_t s1;
    cudaEvent_t eFork, eJoin;
    cudaStreamCreateWithFlags(&s1, cudaStreamNonBlocking);
    cudaEventCreateWithFlags(&eFork, cudaEventDisableTiming);
    cudaEventCreateWithFlags(&eJoin, cudaEventDisableTiming);

    cudaEventRecord(eFork, 0);
    cudaStreamWaitEvent(s1, eFork, 0);

    // stream 0: t-path conversions + t-proj
    cvt_h_kernel<<<(BL_*E_/8 + 255)/256, 256>>>(xt, xth, BL_*E_/8);
    cvt_h_kernel<<<(E_*3*E_/8 + 255)/256, 256>>>(Wt, WtT, E_*3*E_/8);
    // side stream: s-path + epilogue-weight conversions (independent)
    cvt_h_kernel<<<(BL_*E_/8 + 255)/256, 256, 0, s1>>>(xs, xsh, BL_*E_/8);
    cvt_h_kernel<<<(E_*2*E_/8 + 255)/256, 256, 0, s1>>>(Ws, WsT, E_*2*E_/8);
    cvt_h_kernel<<<(E_*E_/8 + 255)/256, 256, 0, s1>>>(Wc, WcT, E_*E_/8);
    cudaEventRecord(eJoin, s1);

    // 1) t-proj: xt @ Wt + bt -> fused pack (Q left, K' both halves, V)
    gemm_h<1><<<dim3(3*E_/128, BL_/128), 256, GEMM_SMEM>>>(
        xth, WtT, bt, nullptr, lst, nullptr, 3*E_, E_);

    // join side stream before s-proj (needs xsh/WsT; RMW also needs gemm1 done)
    cudaStreamWaitEvent(0, eJoin, 0);

    // 2) s-proj: xs @ Ws + bs -> fused pack (Q right, K' RMW)
    gemm_h<2><<<dim3(2*E_/128, BL_/128), 256, GEMM_SMEM>>>(
        xsh, WsT, bs, nullptr, lts, lss, 2*E_, E_);
    // 3) attention
    attn_h<<<dim3(L_/128, BH_), 256, ATTN_SMEM>>>();
    // 4) y @ Wc + bc -> out
    gemm_h<0><<<dim3(E_/128, BL_/128), 256, GEMM_SMEM>>>(
        y, WcT, bc, out, nullptr, nullptr, E_, E_);

    cudaEventDestroy(eFork);
    cudaEventDestroy(eJoin);
    cudaStreamDestroy(s1);
}

// round 12
// speedup vs baseline: 7.7383x; 1.0362x over previous
#include <cuda_runtime.h>
#include <cuda_fp16.h>
#include <cstdint>

#define B_ 2
#define L_ 2048
#define E_ 1024
#define H_ 16
#define D_ 64
#define BL_ (B_*L_)
#define BH_ (B_*H_)

// ---------------- scratch (device globals) ---------------------------------
__device__ __half g_Qp[(size_t)BH_ * L_ * 128];
__device__ __half g_Kp[(size_t)BH_ * L_ * 128];
__device__ __half g_Vp[(size_t)BH_ * L_ * 64];
__device__ __half g_y [(size_t)BL_ * E_];
__device__ __half g_xth[(size_t)BL_ * E_];
__device__ __half g_xsh[(size_t)BL_ * E_];
__device__ __half g_WtT[(size_t)E_ * 3*E_];
__device__ __half g_WsT[(size_t)E_ * 2*E_];
__device__ __half g_WcT[(size_t)E_ * E_];

// Q scale: 1/sqrt(64) * log2(e)  (softmax runs in base-2 domain)
#define QS 0.18033688011112042f

// ---------------- helpers ----------------------------------------------------
union H2U { __half2 h; uint32_t u; };
__device__ __forceinline__ uint32_t h2u(__half2 v){ H2U x; x.h = v; return x.u; }
__device__ __forceinline__ __half2 u2h(uint32_t v){ H2U x; x.u = v; return x.h; }

__device__ __forceinline__ float ex2f(float x){
    float r; asm("ex2.approx.f32 %0, %1;" : "=f"(r) : "f"(x)); return r;
}
// packed fp16x2 2^x — one MUFU op for two exponentials
__device__ __forceinline__ uint32_t h2ex2(uint32_t x){
    uint32_t r; asm("ex2.approx.f16x2 %0, %1;" : "=r"(r) : "r"(x)); return r;
}
__device__ __forceinline__ void mma_f16(float c[4],
    uint32_t a0,uint32_t a1,uint32_t a2,uint32_t a3,uint32_t b0,uint32_t b1){
    asm volatile("mma.sync.aligned.m16n8k16.row.col.f32.f16.f16.f32 "
        "{%0,%1,%2,%3}, {%4,%5,%6,%7}, {%8,%9}, {%0,%1,%2,%3};"
        : "+f"(c[0]),"+f"(c[1]),"+f"(c[2]),"+f"(c[3])
        : "r"(a0),"r"(a1),"r"(a2),"r"(a3),"r"(b0),"r"(b1));
}
__device__ __forceinline__ void ldsm4(uint32_t& r0,uint32_t& r1,uint32_t& r2,uint32_t& r3,
                                      uint32_t addr){
    asm volatile("ldmatrix.sync.aligned.m8n8.x4.shared.b16 {%0,%1,%2,%3}, [%4];"
        : "=r"(r0),"=r"(r1),"=r"(r2),"=r"(r3) : "r"(addr));
}
__device__ __forceinline__ void ldsm4t(uint32_t& r0,uint32_t& r1,uint32_t& r2,uint32_t& r3,
                                       uint32_t addr){
    asm volatile("ldmatrix.sync.aligned.m8n8.x4.trans.shared.b16 {%0,%1,%2,%3}, [%4];"
        : "=r"(r0),"=r"(r1),"=r"(r2),"=r"(r3) : "r"(addr));
}
__device__ __forceinline__ void cp16(uint32_t dst, const void* src){
    asm volatile("cp.async.cg.shared.global [%0], [%1], 16;" :: "r"(dst), "l"(src));
}
__device__ __forceinline__ void cp_commit(){ asm volatile("cp.async.commit_group;"); }
template<int N> __device__ __forceinline__ void cp_wait(){
    asm volatile("cp.async.wait_group %0;" :: "n"(N));
}
__device__ __forceinline__ uint32_t s2u(const void* p){
    return (uint32_t)__cvta_generic_to_shared(p);
}

// ---------------- fp32 -> fp16 conversion (16 elems/thread, MLP=4) ----------
__global__ __launch_bounds__(256) void cvt_h_kernel(
    const float* __restrict__ in, __half* __restrict__ out, int n16)
{
    int i = blockIdx.x*blockDim.x + threadIdx.x;
    if (i < n16){
        const float4* p = (const float4*)(in + (size_t)i*16);
        float4 a = p[0], b = p[1], c = p[2], d = p[3];
        __half2 h[8];
        h[0] = __floats2half2_rn(a.x, a.y);
        h[1] = __floats2half2_rn(a.z, a.w);
        h[2] = __floats2half2_rn(b.x, b.y);
        h[3] = __floats2half2_rn(b.z, b.w);
        h[4] = __floats2half2_rn(c.x, c.y);
        h[5] = __floats2half2_rn(c.z, c.w);
        h[6] = __floats2half2_rn(d.x, d.y);
        h[7] = __floats2half2_rn(d.z, d.w);
        *(float4*)(out + (size_t)i*16)     = *(float4*)h;
        *(float4*)(out + (size_t)i*16 + 8) = *(float4*)(h+4);
    }
}

// ---------------- GEMM core: fp16 mma, 3-stage, 1 sync/iter ------------------
// BM=128, BN=128, BK=32(half), 8 warps (2x4), warp tile 64x32.
// MODE 0: fp32 C + bias.  MODE 1: t-proj fused epilogue.  MODE 2: s-proj RMW.
#define ASTR 40
#define BSTR 136
#define GH_STAGE (128*ASTR + 32*BSTR)     // halfs per stage
template<int MODE>
__global__ __launch_bounds__(256, 2) void gemm_h(
    const __half* __restrict__ A, const __half* __restrict__ W,
    const float* __restrict__ bias, float* __restrict__ C,
    const float* __restrict__ lamA, const float* __restrict__ lamB,
    int N, int K)
{
    extern __shared__ __half smh[];
    const int tid = threadIdx.x, lane = tid & 31, warp = tid >> 5;
    const int wm = warp >> 2, wn = warp & 3, gid = lane >> 2, tig = lane & 3;
    const int bM = blockIdx.y * 128, bN = blockIdx.x * 128;
    const uint32_t sbase = s2u(smh);

    float c[4][4][4];
#pragma unroll
    for (int i=0;i<4;i++)
#pragma unroll
        for (int j=0;j<4;j++)
#pragma unroll
            for (int r=0;r<4;r++) c[i][j][r]=0.f;

    const int niter = K >> 5;
    const int lrow = (lane & 7) + ((lane >> 3) & 1) * 8;
    const int lcol = (lane >> 4) * 8;

    auto load_chunk = [&](int ch_k, int s){
        const uint32_t aBuf = sbase + (uint32_t)(s*GH_STAGE)*2;
        const uint32_t bBuf = aBuf + (uint32_t)(128*ASTR)*2;
        const int k0 = ch_k * 32;
#pragma unroll
        for (int i=0;i<2;i++){
            int ch = tid + i*256, row = ch>>2, colh = (ch&3)*8;
            cp16(aBuf + (uint32_t)(row*ASTR + colh)*2,
                 A + (size_t)(bM+row)*K + k0 + colh);
        }
#pragma unroll
        for (int i=0;i<2;i++){
            int ch = tid + i*256, row = ch>>4, colh = (ch&15)*8;
            cp16(bBuf + (uint32_t)(row*BSTR + colh)*2,
                 W + (size_t)(k0+row)*N + bN + colh);
        }
        cp_commit();
    };

    load_chunk(0, 0);
    load_chunk(1, 1);

    for (int it = 0; it < niter; it++){
        if (it < niter-1) cp_wait<1>(); else cp_wait<0>();
        __syncthreads();
        if (it + 2 < niter) load_chunk(it+2, (it+2)%3);

        const int s = it % 3;
        const uint32_t aBase = sbase + (uint32_t)(s*GH_STAGE)*2;
        const uint32_t bBase = aBase + (uint32_t)(128*ASTR)*2;
#pragma unroll
        for (int kk = 0; kk < 2; kk++){
            const int kb = kk*16;
            uint32_t a[4][4], b[4][2];
#pragma unroll
            for (int i=0;i<4;i++){
                const int r = wm*64 + i*16 + lrow;
                ldsm4(a[i][0],a[i][1],a[i][2],a[i][3],
                      aBase + (uint32_t)(r*ASTR + kb + lcol)*2);
            }
#pragma unroll
            for (int jj=0;jj<2;jj++){
                const int krow = kb + lrow;
                const int nc = wn*32 + jj*16 + lcol;
                uint32_t r0,r1,r2,r3;
                ldsm4t(r0,r1,r2,r3, bBase + (uint32_t)(krow*BSTR + nc)*2);
                b[jj*2  ][0]=r0; b[jj*2  ][1]=r1;
                b[jj*2+1][0]=r2; b[jj*2+1][1]=r3;
            }
#pragma unroll
            for (int i=0;i<4;i++)
#pragma unroll
                for (int j=0;j<4;j++)
                    mma_f16(c[i][j], a[i][0],a[i][1],a[i][2],a[i][3], b[j][0],b[j][1]);
        }
    }

    // -------- epilogue --------
    const float lA = (MODE != 0) ? lamA[0] : 0.f;
    const float lB = (MODE == 2) ? lamB[0] : 0.f;
#pragma unroll
    for (int i=0;i<4;i++){
        const int row0 = bM + wm*64 + i*16 + gid;
#pragma unroll
        for (int j=0;j<4;j++){
            const int col = bN + wn*32 + j*8 + tig*2;
            const float b0 = bias[col], b1 = bias[col+1];
#pragma unroll
            for (int half_ = 0; half_ < 2; half_++){
                const int r = row0 + half_*8;
                const float v0 = c[i][j][half_*2  ] + b0;
                const float v1 = c[i][j][half_*2+1] + b1;
                if (MODE == 0){
                    *(float2*)(C + (size_t)r*N + col) = make_float2(v0, v1);
                } else {
                    const int bb = r >> 11, l = r & 2047;
                    if (MODE == 1){
                        if (col < 1024){
                            const int h = col>>6, d = col&63;
                            const size_t o = ((size_t)((bb<<4)+h)*L_ + l)*128 + d;
                            *(__half2*)&g_Qp[o] = __floats2half2_rn(v0*QS, v1*QS);
                        } else if (col < 2048){
                            const int cc = col-1024, h = cc>>6, d = cc&63;
                            const size_t o = ((size_t)((bb<<4)+h)*L_ + l)*128 + d;
                            *(__half2*)&g_Kp[o]    = __floats2half2_rn(v0, v1);
                            *(__half2*)&g_Kp[o+64] = __floats2half2_rn(lA*v0, lA*v1);
                        } else {
                            const int cc = col-2048, h = cc>>6, d = cc&63;
                            const size_t o = ((size_t)((bb<<4)+h)*L_ + l)*64 + d;
                            *(__half2*)&g_Vp[o] = __floats2half2_rn(v0, v1);
                        }
                    } else { // MODE 2
                        if (col < 1024){
                            const int h = col>>6, d = col&63;
                            const size_t o = ((size_t)((bb<<4)+h)*L_ + l)*128 + 64 + d;
                            *(__half2*)&g_Qp[o] = __floats2half2_rn(v0*QS, v1*QS);
                        } else {
                            const int cc = col-1024, h = cc>>6, d = cc&63;
                            const size_t o = ((size_t)((bb<<4)+h)*L_ + l)*128 + d;
                            float2 f0 = __half22float2(*(__half2*)&g_Kp[o]);
                            *(__half2*)&g_Kp[o] =
                                __floats2half2_rn(f0.x + lA*v0, f0.y + lA*v1);
                            float2 f1 = __half22float2(*(__half2*)&g_Kp[o+64]);
                            *(__half2*)&g_Kp[o+64] =
                                __floats2half2_rn(f1.x + lB*v0, f1.y + lB*v1);
                        }
                    }
                }
            }
        }
    }
}

// ---------------- flash attention: BQ=128, BK=64, 3-stage, 1 sync/tile ------
#define KSTR 136
#define VSTR 72
#define AT_STAGE (64*KSTR + 64*VSTR)      // halfs per stage
#define NT 32
__global__ __launch_bounds__(256, 2) void attn_h()
{
    extern __shared__ __half smh[];
    const int tid = threadIdx.x, lane = tid & 31, warp = tid >> 5;
    const int gid = lane >> 2, tig = lane & 3;
    const int bh = blockIdx.y, q0 = blockIdx.x * 128;
    const int w16 = warp * 16;
    const int lrow = (lane & 7) + ((lane >> 3) & 1) * 8;
    const int lcol = (lane >> 4) * 8;

    const __half* Qg = g_Qp + (size_t)bh * L_ * 128;
    const __half* Kg = g_Kp + (size_t)bh * L_ * 128;
    const __half* Vg = g_Vp + (size_t)bh * L_ * 64;
    const uint32_t sbase = s2u(smh);

    uint32_t qa[8][4];
    {
        const __half* q0p = Qg + (size_t)(q0 + w16 + gid)*128;
        const __half* q1p = q0p + 8*128;
#pragma unroll
        for (int kk=0;kk<8;kk++){
            qa[kk][0] = *(const uint32_t*)(q0p + kk*16 + 2*tig);
            qa[kk][1] = *(const uint32_t*)(q1p + kk*16 + 2*tig);
            qa[kk][2] = *(const uint32_t*)(q0p + kk*16 + 8 + 2*tig);
            qa[kk][3] = *(const uint32_t*)(q1p + kk*16 + 8 + 2*tig);
        }
    }

    auto load_tile = [&](int t, int s){
        const uint32_t kBuf = sbase + (uint32_t)(s*AT_STAGE)*2;
        const uint32_t vBuf = kBuf + (uint32_t)(64*KSTR)*2;
        const int r0g = t*64;
#pragma unroll
        for (int i=0;i<4;i++){
            int ch = tid + i*256, row = ch>>4, colh = (ch&15)*8;
            cp16(kBuf + (uint32_t)(row*KSTR + colh)*2,
                 Kg + (size_t)(r0g+row)*128 + colh);
        }
#pragma unroll
        for (int i=0;i<2;i++){
            int ch = tid + i*256, row = ch>>3, colh = (ch&7)*8;
            cp16(vBuf + (uint32_t)(row*VSTR + colh)*2,
                 Vg + (size_t)(r0g+row)*64 + colh);
        }
        cp_commit();
    };

    float o[8][4];
#pragma unroll
    for (int j=0;j<8;j++){ o[j][0]=0.f; o[j][1]=0.f; o[j][2]=0.f; o[j][3]=0.f; }
    float mA = -1e30f, mB = -1e30f, lA = 0.f, lB = 0.f;

    load_tile(0, 0);
    load_tile(1, 1);

    for (int t = 0; t < NT; t++){
        if (t < NT-1) cp_wait<1>(); else cp_wait<0>();
        __syncthreads();
        if (t + 2 < NT) load_tile(t+2, (t+2)%3);

        const int s = t % 3;
        const uint32_t kBase = sbase + (uint32_t)(s*AT_STAGE)*2;
        const uint32_t vBase = kBase + (uint32_t)(64*KSTR)*2;

        // S = Q @ K^T
        float sc[8][4];
#pragma unroll
        for (int j=0;j<8;j++){ sc[j][0]=0.f; sc[j][1]=0.f; sc[j][2]=0.f; sc[j][3]=0.f; }
        const int krow = (lane & 7) + (lane >> 4) * 8;
        const int kcol = ((lane >> 3) & 1) * 8;
#pragma unroll
        for (int kk=0;kk<8;kk++){
            const int kb = kk*16;
#pragma unroll
            for (int jj=0;jj<4;jj++){
                uint32_t b0,b1,b2,b3;
                ldsm4(b0,b1,b2,b3,
                    kBase + (uint32_t)((jj*16 + krow)*KSTR + kb + kcol)*2);
                mma_f16(sc[jj*2  ], qa[kk][0],qa[kk][1],qa[kk][2],qa[kk][3], b0,b1);
                mma_f16(sc[jj*2+1], qa[kk][0],qa[kk][1],qa[kk][2],qa[kk][3], b2,b3);
            }
        }

        // online softmax (base-2 domain)
        float rmA = -1e30f, rmB = -1e30f;
#pragma unroll
        for (int j=0;j<8;j++){
            rmA = fmaxf(rmA, fmaxf(sc[j][0], sc[j][1]));
            rmB = fmaxf(rmB, fmaxf(sc[j][2], sc[j][3]));
        }
        rmA = fmaxf(rmA, __shfl_xor_sync(0xffffffffu, rmA, 1));
        rmA = fmaxf(rmA, __shfl_xor_sync(0xffffffffu, rmA, 2));
        rmB = fmaxf(rmB, __shfl_xor_sync(0xffffffffu, rmB, 1));
        rmB = fmaxf(rmB, __shfl_xor_sync(0xffffffffu, rmB, 2));
        const float nmA = fmaxf(mA, rmA), nmB = fmaxf(mB, rmB);
        const float aA = ex2f(mA - nmA), aB = ex2f(mB - nmB);
        mA = nmA; mB = nmB;

        // packed fp16 exponentials: outputs ARE the P mma fragments
        uint32_t pa[4][4];
        float sumA = 0.f, sumB = 0.f;
#pragma unroll
        for (int kk=0;kk<4;kk++){
            uint32_t e0 = h2ex2(h2u(__floats2half2_rn(sc[2*kk  ][0]-nmA, sc[2*kk  ][1]-nmA)));
            uint32_t e1 = h2ex2(h2u(__floats2half2_rn(sc[2*kk  ][2]-nmB, sc[2*kk  ][3]-nmB)));
            uint32_t e2 = h2ex2(h2u(__floats2half2_rn(sc[2*kk+1][0]-nmA, sc[2*kk+1][1]-nmA)));
            uint32_t e3 = h2ex2(h2u(__floats2half2_rn(sc[2*kk+1][2]-nmB, sc[2*kk+1][3]-nmB)));
            pa[kk][0]=e0; pa[kk][1]=e1; pa[kk][2]=e2; pa[kk][3]=e3;
            float2 f;
            f = __half22float2(u2h(e0)); sumA += f.x + f.y;
            f = __half22float2(u2h(e2)); sumA += f.x + f.y;
            f = __half22float2(u2h(e1)); sumB += f.x + f.y;
            f = __half22float2(u2h(e3)); sumB += f.x + f.y;
        }
#pragma unroll
        for (int j=0;j<8;j++){
            o[j][0]*=aA; o[j][1]*=aA; o[j][2]*=aB; o[j][3]*=aB;
        }
        sumA += __shfl_xor_sync(0xffffffffu, sumA, 1);
        sumA += __shfl_xor_sync(0xffffffffu, sumA, 2);
        sumB += __shfl_xor_sync(0xffffffffu, sumB, 1);
        sumB += __shfl_xor_sync(0xffffffffu, sumB, 2);
        lA = lA*aA + sumA; lB = lB*aB + sumB;

        // O += P @ V
#pragma unroll
        for (int kk=0;kk<4;kk++){
            const int kb = kk*16;
#pragma unroll
            for (int jj=0;jj<4;jj++){
                uint32_t b0,b1,b2,b3;
                ldsm4t(b0,b1,b2,b3,
                    vBase + (uint32_t)((kb + lrow)*VSTR + jj*16 + lcol)*2);
                mma_f16(o[jj*2  ], pa[kk][0],pa[kk][1],pa[kk][2],pa[kk][3], b0,b1);
                mma_f16(o[jj*2+1], pa[kk][0],pa[kk][1],pa[kk][2],pa[kk][3], b2,b3);
            }
        }
    }

    const int b = bh / H_, h = bh % H_;
    const float iA = 1.f/lA, iB = 1.f/lB;
    const int rowA = b*L_ + q0 + w16 + gid;
#pragma unroll
    for (int j=0;j<8;j++){
        const int col = h*64 + j*8 + tig*2;
        __half2 vA = __floats2half2_rn(o[j][0]*iA, o[j][1]*iA);
        __half2 vB = __floats2half2_rn(o[j][2]*iB, o[j][3]*iB);
        *(__half2*)&g_y[(size_t)rowA    *E_ + col] = vA;
        *(__half2*)&g_y[(size_t)(rowA+8)*E_ + col] = vB;
    }
}

// ---------------- launch ----------------------------------------------------
extern "C" void kernel_launch(void* const* d_in, const int* in_sizes, int n_in,
                              void* d_out, int out_size)
{
    const float* xt  = (const float*)d_in[0];
    const float* xs  = (const float*)d_in[1];
    const float* Wt  = (const float*)d_in[2];
    const float* bt  = (const float*)d_in[3];
    const float* Ws  = (const float*)d_in[4];
    const float* bs  = (const float*)d_in[5];
    const float* Wc  = (const float*)d_in[6];
    const float* bc  = (const float*)d_in[7];
    const float* lts = (const float*)d_in[8];
    const float* lst = (const float*)d_in[9];
    const float* lss = (const float*)d_in[10];
    float* out = (float*)d_out;

    __half *y, *xth, *xsh, *WtT, *WsT, *WcT;
    cudaGetSymbolAddress((void**)&y,    g_y);
    cudaGetSymbolAddress((void**)&xth,  g_xth);
    cudaGetSymbolAddress((void**)&xsh,  g_xsh);
    cudaGetSymbolAddress((void**)&WtT,  g_WtT);
    cudaGetSymbolAddress((void**)&WsT,  g_WsT);
    cudaGetSymbolAddress((void**)&WcT,  g_WcT);

    const int GEMM_SMEM = 3 * GH_STAGE * 2;    // 56832 B
    const int ATTN_SMEM = 3 * AT_STAGE * 2;    // 79872 B
    cudaFuncSetAttribute(gemm_h<0>,
        cudaFuncAttributeMaxDynamicSharedMemorySize, GEMM_SMEM);
    cudaFuncSetAttribute(gemm_h<1>,
        cudaFuncAttributeMaxDynamicSharedMemorySize, GEMM_SMEM);
    cudaFuncSetAttribute(gemm_h<2>,
        cudaFuncAttributeMaxDynamicSharedMemorySize, GEMM_SMEM);
    cudaFuncSetAttribute(attn_h,
        cudaFuncAttributeMaxDynamicSharedMemorySize, ATTN_SMEM);

    // ---- fork side stream for independent s/c-path conversions --------------
    cudaStream_t s1;
    cudaEvent_t eFork, eJoin;
    cudaStreamCreateWithFlags(&s1, cudaStreamNonBlocking);
    cudaEventCreateWithFlags(&eFork, cudaEventDisableTiming);
    cudaEventCreateWithFlags(&eJoin, cudaEventDisableTiming);

    cudaEventRecord(eFork, 0);
    cudaStreamWaitEvent(s1, eFork, 0);

    // stream 0: t-path conversions + t-proj
    cvt_h_kernel<<<(BL_*E_/16 + 255)/256, 256>>>(xt, xth, BL_*E_/16);
    cvt_h_kernel<<<(E_*3*E_/16 + 255)/256, 256>>>(Wt, WtT, E_*3*E_/16);
    // side stream: s-path + epilogue-weight conversions (independent)
    cvt_h_kernel<<<(BL_*E_/16 + 255)/256, 256, 0, s1>>>(xs, xsh, BL_*E_/16);
    cvt_h_kernel<<<(E_*2*E_/16 + 255)/256, 256, 0, s1>>>(Ws, WsT, E_*2*E_/16);
    cvt_h_kernel<<<(E_*E_/16 + 255)/256, 256, 0, s1>>>(Wc, WcT, E_*E_/16);
    cudaEventRecord(eJoin, s1);

    // 1) t-proj: xt @ Wt + bt -> fused pack (Q left, K' both halves, V)
    gemm_h<1><<<dim3(3*E_/128, BL_/128), 256, GEMM_SMEM>>>(
        xth, WtT, bt, nullptr, lst, nullptr, 3*E_, E_);

    // join side stream before s-proj (needs xsh/WsT; RMW also needs gemm1 done)
    cudaStreamWaitEvent(0, eJoin, 0);

    // 2) s-proj: xs @ Ws + bs -> fused pack (Q right, K' RMW)
    gemm_h<2><<<dim3(2*E_/128, BL_/128), 256, GEMM_SMEM>>>(
        xsh, WsT, bs, nullptr, lts, lss, 2*E_, E_);
    // 3) attention
    attn_h<<<dim3(L_/128, BH_), 256, ATTN_SMEM>>>();
    // 4) y @ Wc + bc -> out
    gemm_h<0><<<dim3(E_/128, BL_/128), 256, GEMM_SMEM>>>(
        y, WcT, bc, out, nullptr, nullptr, E_, E_);

    cudaEventDestroy(eFork);
    cudaEventDestroy(eJoin);
    cudaStreamDestroy(s1);
}

// round 13
// speedup vs baseline: 7.7733x; 1.0045x over previous
#include <cuda_runtime.h>
#include <cuda_fp16.h>
#include <cstdint>

#define B_ 2
#define L_ 2048
#define E_ 1024
#define H_ 16
#define D_ 64
#define BL_ (B_*L_)
#define BH_ (B_*H_)

// ---------------- scratch (device globals) ---------------------------------
__device__ __half g_Qp[(size_t)BH_ * L_ * 128];
__device__ __half g_Kt[(size_t)BH_ * L_ * 64];   // raw kt  (t-proj)
__device__ __half g_Ks[(size_t)BH_ * L_ * 64];   // raw ks  (s-proj)
__device__ __half g_Vp[(size_t)BH_ * L_ * 64];
__device__ __half g_y [(size_t)BL_ * E_];
__device__ __half g_xth[(size_t)BL_ * E_];
__device__ __half g_xsh[(size_t)BL_ * E_];
__device__ __half g_WtT[(size_t)E_ * 3*E_];
__device__ __half g_WsT[(size_t)E_ * 2*E_];
__device__ __half g_WcT[(size_t)E_ * E_];

// Q scale: 1/sqrt(64) * log2(e)  (softmax runs in base-2 domain)
#define QS 0.18033688011112042f

// ---------------- helpers ----------------------------------------------------
union H2U { __half2 h; uint32_t u; };
__device__ __forceinline__ uint32_t h2u(__half2 v){ H2U x; x.h = v; return x.u; }
__device__ __forceinline__ __half2 u2h(uint32_t v){ H2U x; x.u = v; return x.h; }

__device__ __forceinline__ float ex2f(float x){
    float r; asm("ex2.approx.f32 %0, %1;" : "=f"(r) : "f"(x)); return r;
}
__device__ __forceinline__ uint32_t h2ex2(uint32_t x){
    uint32_t r; asm("ex2.approx.f16x2 %0, %1;" : "=r"(r) : "r"(x)); return r;
}
__device__ __forceinline__ void mma_f16(float c[4],
    uint32_t a0,uint32_t a1,uint32_t a2,uint32_t a3,uint32_t b0,uint32_t b1){
    asm volatile("mma.sync.aligned.m16n8k16.row.col.f32.f16.f16.f32 "
        "{%0,%1,%2,%3}, {%4,%5,%6,%7}, {%8,%9}, {%0,%1,%2,%3};"
        : "+f"(c[0]),"+f"(c[1]),"+f"(c[2]),"+f"(c[3])
        : "r"(a0),"r"(a1),"r"(a2),"r"(a3),"r"(b0),"r"(b1));
}
__device__ __forceinline__ void ldsm4(uint32_t& r0,uint32_t& r1,uint32_t& r2,uint32_t& r3,
                                      uint32_t addr){
    asm volatile("ldmatrix.sync.aligned.m8n8.x4.shared.b16 {%0,%1,%2,%3}, [%4];"
        : "=r"(r0),"=r"(r1),"=r"(r2),"=r"(r3) : "r"(addr));
}
__device__ __forceinline__ void ldsm4t(uint32_t& r0,uint32_t& r1,uint32_t& r2,uint32_t& r3,
                                       uint32_t addr){
    asm volatile("ldmatrix.sync.aligned.m8n8.x4.trans.shared.b16 {%0,%1,%2,%3}, [%4];"
        : "=r"(r0),"=r"(r1),"=r"(r2),"=r"(r3) : "r"(addr));
}
__device__ __forceinline__ void cp16(uint32_t dst, const void* src){
    asm volatile("cp.async.cg.shared.global [%0], [%1], 16;" :: "r"(dst), "l"(src));
}
__device__ __forceinline__ void cp_commit(){ asm volatile("cp.async.commit_group;"); }
template<int N> __device__ __forceinline__ void cp_wait(){
    asm volatile("cp.async.wait_group %0;" :: "n"(N));
}
__device__ __forceinline__ uint32_t s2u(const void* p){
    return (uint32_t)__cvta_generic_to_shared(p);
}

// ---------------- fp32 -> fp16 conversion (16 elems/thread, MLP=4) ----------
__global__ __launch_bounds__(256) void cvt_h_kernel(
    const float* __restrict__ in, __half* __restrict__ out, int n16)
{
    int i = blockIdx.x*blockDim.x + threadIdx.x;
    if (i < n16){
        const float4* p = (const float4*)(in + (size_t)i*16);
        float4 a = p[0], b = p[1], c = p[2], d = p[3];
        __half2 h[8];
        h[0] = __floats2half2_rn(a.x, a.y);
        h[1] = __floats2half2_rn(a.z, a.w);
        h[2] = __floats2half2_rn(b.x, b.y);
        h[3] = __floats2half2_rn(b.z, b.w);
        h[4] = __floats2half2_rn(c.x, c.y);
        h[5] = __floats2half2_rn(c.z, c.w);
        h[6] = __floats2half2_rn(d.x, d.y);
        h[7] = __floats2half2_rn(d.z, d.w);
        *(float4*)(out + (size_t)i*16)     = *(float4*)h;
        *(float4*)(out + (size_t)i*16 + 8) = *(float4*)(h+4);
    }
}

// ---------------- GEMM core: fp16 mma, 3-stage, 1 sync/iter ------------------
// BM=128, BN=128, BK=32(half), 8 warps (2x4), warp tile 64x32.
// MODE 0: fp32 C + bias. MODE 1: t-proj -> Qp-left/Kt/Vp. MODE 2: s-proj -> Qp-right/Ks.
#define ASTR 40
#define BSTR 136
#define GH_STAGE (128*ASTR + 32*BSTR)     // halfs per stage
template<int MODE>
__global__ __launch_bounds__(256, 2) void gemm_h(
    const __half* __restrict__ A, const __half* __restrict__ W,
    const float* __restrict__ bias, float* __restrict__ C,
    int N, int K)
{
    extern __shared__ __half smh[];
    const int tid = threadIdx.x, lane = tid & 31, warp = tid >> 5;
    const int wm = warp >> 2, wn = warp & 3, gid = lane >> 2, tig = lane & 3;
    const int bM = blockIdx.y * 128, bN = blockIdx.x * 128;
    const uint32_t sbase = s2u(smh);

    float c[4][4][4];
#pragma unroll
    for (int i=0;i<4;i++)
#pragma unroll
        for (int j=0;j<4;j++)
#pragma unroll
            for (int r=0;r<4;r++) c[i][j][r]=0.f;

    const int niter = K >> 5;
    const int lrow = (lane & 7) + ((lane >> 3) & 1) * 8;
    const int lcol = (lane >> 4) * 8;

    auto load_chunk = [&](int ch_k, int s){
        const uint32_t aBuf = sbase + (uint32_t)(s*GH_STAGE)*2;
        const uint32_t bBuf = aBuf + (uint32_t)(128*ASTR)*2;
        const int k0 = ch_k * 32;
#pragma unroll
        for (int i=0;i<2;i++){
            int ch = tid + i*256, row = ch>>2, colh = (ch&3)*8;
            cp16(aBuf + (uint32_t)(row*ASTR + colh)*2,
                 A + (size_t)(bM+row)*K + k0 + colh);
        }
#pragma unroll
        for (int i=0;i<2;i++){
            int ch = tid + i*256, row = ch>>4, colh = (ch&15)*8;
            cp16(bBuf + (uint32_t)(row*BSTR + colh)*2,
                 W + (size_t)(k0+row)*N + bN + colh);
        }
        cp_commit();
    };

    load_chunk(0, 0);
    load_chunk(1, 1);

    for (int it = 0; it < niter; it++){
        if (it < niter-1) cp_wait<1>(); else cp_wait<0>();
        __syncthreads();
        if (it + 2 < niter) load_chunk(it+2, (it+2)%3);

        const int s = it % 3;
        const uint32_t aBase = sbase + (uint32_t)(s*GH_STAGE)*2;
        const uint32_t bBase = aBase + (uint32_t)(128*ASTR)*2;
#pragma unroll
        for (int kk = 0; kk < 2; kk++){
            const int kb = kk*16;
            uint32_t a[4][4], b[4][2];
#pragma unroll
            for (int i=0;i<4;i++){
                const int r = wm*64 + i*16 + lrow;
                ldsm4(a[i][0],a[i][1],a[i][2],a[i][3],
                      aBase + (uint32_t)(r*ASTR + kb + lcol)*2);
            }
#pragma unroll
            for (int jj=0;jj<2;jj++){
                const int krow = kb + lrow;
                const int nc = wn*32 + jj*16 + lcol;
                uint32_t r0,r1,r2,r3;
                ldsm4t(r0,r1,r2,r3, bBase + (uint32_t)(krow*BSTR + nc)*2);
                b[jj*2  ][0]=r0; b[jj*2  ][1]=r1;
                b[jj*2+1][0]=r2; b[jj*2+1][1]=r3;
            }
#pragma unroll
            for (int i=0;i<4;i++)
#pragma unroll
                for (int j=0;j<4;j++)
                    mma_f16(c[i][j], a[i][0],a[i][1],a[i][2],a[i][3], b[j][0],b[j][1]);
        }
    }

    // -------- epilogue --------
#pragma unroll
    for (int i=0;i<4;i++){
        const int row0 = bM + wm*64 + i*16 + gid;
#pragma unroll
        for (int j=0;j<4;j++){
            const int col = bN + wn*32 + j*8 + tig*2;
            const float b0 = bias[col], b1 = bias[col+1];
#pragma unroll
            for (int half_ = 0; half_ < 2; half_++){
                const int r = row0 + half_*8;
                const float v0 = c[i][j][half_*2  ] + b0;
                const float v1 = c[i][j][half_*2+1] + b1;
                if (MODE == 0){
                    *(float2*)(C + (size_t)r*N + col) = make_float2(v0, v1);
                } else {
                    const int bb = r >> 11, l = r & 2047;
                    if (MODE == 1){
                        if (col < 1024){
                            const int h = col>>6, d = col&63;
                            const size_t o = ((size_t)((bb<<4)+h)*L_ + l)*128 + d;
                            *(__half2*)&g_Qp[o] = __floats2half2_rn(v0*QS, v1*QS);
                        } else if (col < 2048){
                            const int cc = col-1024, h = cc>>6, d = cc&63;
                            const size_t o = ((size_t)((bb<<4)+h)*L_ + l)*64 + d;
                            *(__half2*)&g_Kt[o] = __floats2half2_rn(v0, v1);
                        } else {
                            const int cc = col-2048, h = cc>>6, d = cc&63;
                            const size_t o = ((size_t)((bb<<4)+h)*L_ + l)*64 + d;
                            *(__half2*)&g_Vp[o] = __floats2half2_rn(v0, v1);
                        }
                    } else { // MODE 2
                        if (col < 1024){
                            const int h = col>>6, d = col&63;
                            const size_t o = ((size_t)((bb<<4)+h)*L_ + l)*128 + 64 + d;
                            *(__half2*)&g_Qp[o] = __floats2half2_rn(v0*QS, v1*QS);
                        } else {
                            const int cc = col-1024, h = cc>>6, d = cc&63;
                            const size_t o = ((size_t)((bb<<4)+h)*L_ + l)*64 + d;
                            *(__half2*)&g_Ks[o] = __floats2half2_rn(v0, v1);
                        }
                    }
                }
            }
        }
    }
}

// ---------------- flash attention: BQ=128, BK=64 ----------------------------
// raw kt/ks/v via 2-stage cp.async; fp32 in-kernel lambda combine -> Kc.
// smem (halfs): KtR[2][64*72] | KsR[2][64*72] | Vs[2][64*72] | Kc[64*136]
#define RAWS 4608                 // 64*72
#define OFF_KS (2*RAWS)           // 9216
#define OFF_V  (4*RAWS)           // 18432
#define OFF_KC (6*RAWS)           // 27648
#define KSTR 136
#define VSTR 72
#define ATTN_HALFS (OFF_KC + 64*KSTR)   // 36352 halfs = 72704 B
#define NT 32
__global__ __launch_bounds__(256, 2) void attn_h(
    const float* __restrict__ lam_ts, const float* __restrict__ lam_st,
    const float* __restrict__ lam_ss)
{
    extern __shared__ __half smh[];
    const int tid = threadIdx.x, lane = tid & 31, warp = tid >> 5;
    const int gid = lane >> 2, tig = lane & 3;
    const int bh = blockIdx.y, q0 = blockIdx.x * 128;
    const int w16 = warp * 16;
    const int lrow = (lane & 7) + ((lane >> 3) & 1) * 8;
    const int lcol = (lane >> 4) * 8;

    const float vts = lam_ts[0], vst = lam_st[0], vss = lam_ss[0];

    const __half* Qg  = g_Qp + (size_t)bh * L_ * 128;
    const __half* Ktg = g_Kt + (size_t)bh * L_ * 64;
    const __half* Ksg = g_Ks + (size_t)bh * L_ * 64;
    const __half* Vg  = g_Vp + (size_t)bh * L_ * 64;
    const uint32_t sbase = s2u(smh);
    const uint32_t kcBase = sbase + (uint32_t)OFF_KC*2;

    uint32_t qa[8][4];
    {
        const __half* q0p = Qg + (size_t)(q0 + w16 + gid)*128;
        const __half* q1p = q0p + 8*128;
#pragma unroll
        for (int kk=0;kk<8;kk++){
            qa[kk][0] = *(const uint32_t*)(q0p + kk*16 + 2*tig);
            qa[kk][1] = *(const uint32_t*)(q1p + kk*16 + 2*tig);
            qa[kk][2] = *(const uint32_t*)(q0p + kk*16 + 8 + 2*tig);
            qa[kk][3] = *(const uint32_t*)(q1p + kk*16 + 8 + 2*tig);
        }
    }

    auto load_raw = [&](int t, int s){
        const uint32_t ktB = sbase + (uint32_t)(s*RAWS)*2;
        const uint32_t ksB = sbase + (uint32_t)(OFF_KS + s*RAWS)*2;
        const uint32_t vB  = sbase + (uint32_t)(OFF_V  + s*RAWS)*2;
        const int r0g = t*64;
#pragma unroll
        for (int i=0;i<2;i++){
            int ch = tid + i*256, row = ch>>3, c8 = (ch&7)*8;
            const size_t go = (size_t)(r0g+row)*64 + c8;
            const uint32_t so = (uint32_t)(row*72 + c8)*2;
            cp16(ktB + so, Ktg + go);
            cp16(ksB + so, Ksg + go);
            cp16(vB  + so, Vg  + go);
        }
        cp_commit();
    };

    float o[8][4];
#pragma unroll
    for (int j=0;j<8;j++){ o[j][0]=0.f; o[j][1]=0.f; o[j][2]=0.f; o[j][3]=0.f; }
    float mA = -1e30f, mB = -1e30f, lA = 0.f, lB = 0.f;

    load_raw(0, 0);

    for (int t = 0; t < NT; t++){
        cp_wait<0>();
        __syncthreads();
        if (t + 1 < NT) load_raw(t+1, (t+1)&1);

        // ---- fp32 lambda-combine: raw kt/ks -> Kc [64][136] (k1 | k2) -------
        {
            const int s = t & 1;
            const int key = tid >> 2, q = tid & 3;
            const __half2* ktp = (const __half2*)(smh + s*RAWS + key*72 + q*16);
            const __half2* ksp = (const __half2*)(smh + OFF_KS + s*RAWS + key*72 + q*16);
            __half2 k1h[8], k2h[8];
#pragma unroll
            for (int i=0;i<8;i++){
                float2 a = __half22float2(ktp[i]);
                float2 b = __half22float2(ksp[i]);
                k1h[i] = __floats2half2_rn(a.x + vts*b.x, a.y + vts*b.y);
                k2h[i] = __floats2half2_rn(vst*a.x + vss*b.x, vst*a.y + vss*b.y);
            }
            __half* kc = smh + OFF_KC + key*136 + q*16;
            *(uint4*)(kc)          = *(uint4*)&k1h[0];
            *(uint4*)(kc + 8)      = *(uint4*)&k1h[4];
            *(uint4*)(kc + 64)     = *(uint4*)&k2h[0];
            *(uint4*)(kc + 64 + 8) = *(uint4*)&k2h[4];
        }
        __syncthreads();

        const uint32_t vBase = sbase + (uint32_t)(OFF_V + (t&1)*RAWS)*2;

        // S = Q @ K^T
        float sc[8][4];
#pragma unroll
        for (int j=0;j<8;j++){ sc[j][0]=0.f; sc[j][1]=0.f; sc[j][2]=0.f; sc[j][3]=0.f; }
        const int krow = (lane & 7) + (lane >> 4) * 8;
        const int kcol = ((lane >> 3) & 1) * 8;
#pragma unroll
        for (int kk=0;kk<8;kk++){
            const int kb = kk*16;
#pragma unroll
            for (int jj=0;jj<4;jj++){
                uint32_t b0,b1,b2,b3;
                ldsm4(b0,b1,b2,b3,
                    kcBase + (uint32_t)((jj*16 + krow)*KSTR + kb + kcol)*2);
                mma_f16(sc[jj*2  ], qa[kk][0],qa[kk][1],qa[kk][2],qa[kk][3], b0,b1);
                mma_f16(sc[jj*2+1], qa[kk][0],qa[kk][1],qa[kk][2],qa[kk][3], b2,b3);
            }
        }

        // online softmax (base-2 domain)
        float rmA = -1e30f, rmB = -1e30f;
#pragma unroll
        for (int j=0;j<8;j++){
            rmA = fmaxf(rmA, fmaxf(sc[j][0], sc[j][1]));
            rmB = fmaxf(rmB, fmaxf(sc[j][2], sc[j][3]));
        }
        rmA = fmaxf(rmA, __shfl_xor_sync(0xffffffffu, rmA, 1));
        rmA = fmaxf(rmA, __shfl_xor_sync(0xffffffffu, rmA, 2));
        rmB = fmaxf(rmB, __shfl_xor_sync(0xffffffffu, rmB, 1));
        rmB = fmaxf(rmB, __shfl_xor_sync(0xffffffffu, rmB, 2));
        const float nmA = fmaxf(mA, rmA), nmB = fmaxf(mB, rmB);
        const float aA = ex2f(mA - nmA), aB = ex2f(mB - nmB);
        mA = nmA; mB = nmB;

        uint32_t pa[4][4];
        float sumA = 0.f, sumB = 0.f;
#pragma unroll
        for (int kk=0;kk<4;kk++){
            uint32_t e0 = h2ex2(h2u(__floats2half2_rn(sc[2*kk  ][0]-nmA, sc[2*kk  ][1]-nmA)));
            uint32_t e1 = h2ex2(h2u(__floats2half2_rn(sc[2*kk  ][2]-nmB, sc[2*kk  ][3]-nmB)));
            uint32_t e2 = h2ex2(h2u(__floats2half2_rn(sc[2*kk+1][0]-nmA, sc[2*kk+1][1]-nmA)));
            uint32_t e3 = h2ex2(h2u(__floats2half2_rn(sc[2*kk+1][2]-nmB, sc[2*kk+1][3]-nmB)));
            pa[kk][0]=e0; pa[kk][1]=e1; pa[kk][2]=e2; pa[kk][3]=e3;
            float2 f;
            f = __half22float2(u2h(e0)); sumA += f.x + f.y;
            f = __half22float2(u2h(e2)); sumA += f.x + f.y;
            f = __half22float2(u2h(e1)); sumB += f.x + f.y;
            f = __half22float2(u2h(e3)); sumB += f.x + f.y;
        }
#pragma unroll
        for (int j=0;j<8;j++){
            o[j][0]*=aA; o[j][1]*=aA; o[j][2]*=aB; o[j][3]*=aB;
        }
        sumA += __shfl_xor_sync(0xffffffffu, sumA, 1);
        sumA += __shfl_xor_sync(0xffffffffu, sumA, 2);
        sumB += __shfl_xor_sync(0xffffffffu, sumB, 1);
        sumB += __shfl_xor_sync(0xffffffffu, sumB, 2);
        lA = lA*aA + sumA; lB = lB*aB + sumB;

        // O += P @ V
#pragma unroll
        for (int kk=0;kk<4;kk++){
            const int kb = kk*16;
#pragma unroll
            for (int jj=0;jj<4;jj++){
                uint32_t b0,b1,b2,b3;
                ldsm4t(b0,b1,b2,b3,
                    vBase + (uint32_t)((kb + lrow)*VSTR + jj*16 + lcol)*2);
                mma_f16(o[jj*2  ], pa[kk][0],pa[kk][1],pa[kk][2],pa[kk][3], b0,b1);
                mma_f16(o[jj*2+1], pa[kk][0],pa[kk][1],pa[kk][2],pa[kk][3], b2,b3);
            }
        }
    }

    const int b = bh / H_, h = bh % H_;
    const float iA = 1.f/lA, iB = 1.f/lB;
    const int rowA = b*L_ + q0 + w16 + gid;
#pragma unroll
    for (int j=0;j<8;j++){
        const int col = h*64 + j*8 + tig*2;
        __half2 vA = __floats2half2_rn(o[j][0]*iA, o[j][1]*iA);
        __half2 vB = __floats2half2_rn(o[j][2]*iB, o[j][3]*iB);
        *(__half2*)&g_y[(size_t)rowA    *E_ + col] = vA;
        *(__half2*)&g_y[(size_t)(rowA+8)*E_ + col] = vB;
    }
}

// ---------------- launch ----------------------------------------------------
extern "C" void kernel_launch(void* const* d_in, const int* in_sizes, int n_in,
                              void* d_out, int out_size)
{
    const float* xt  = (const float*)d_in[0];
    const float* xs  = (const float*)d_in[1];
    const float* Wt  = (const float*)d_in[2];
    const float* bt  = (const float*)d_in[3];
    const float* Ws  = (const float*)d_in[4];
    const float* bs  = (const float*)d_in[5];
    const float* Wc  = (const float*)d_in[6];
    const float* bc  = (const float*)d_in[7];
    const float* lts = (const float*)d_in[8];
    const float* lst = (const float*)d_in[9];
    const float* lss = (const float*)d_in[10];
    float* out = (float*)d_out;

    __half *y, *xth, *xsh, *WtT, *WsT, *WcT;
    cudaGetSymbolAddress((void**)&y,    g_y);
    cudaGetSymbolAddress((void**)&xth,  g_xth);
    cudaGetSymbolAddress((void**)&xsh,  g_xsh);
    cudaGetSymbolAddress((void**)&WtT,  g_WtT);
    cudaGetSymbolAddress((void**)&WsT,  g_WsT);
    cudaGetSymbolAddress((void**)&WcT,  g_WcT);

    const int GEMM_SMEM = 3 * GH_STAGE * 2;    // 56832 B
    const int ATTN_SMEM = ATTN_HALFS * 2;      // 72704 B
    cudaFuncSetAttribute(gemm_h<0>,
        cudaFuncAttributeMaxDynamicSharedMemorySize, GEMM_SMEM);
    cudaFuncSetAttribute(gemm_h<1>,
        cudaFuncAttributeMaxDynamicSharedMemorySize, GEMM_SMEM);
    cudaFuncSetAttribute(gemm_h<2>,
        cudaFuncAttributeMaxDynamicSharedMemorySize, GEMM_SMEM);
    cudaFuncSetAttribute(attn_h,
        cudaFuncAttributeMaxDynamicSharedMemorySize, ATTN_SMEM);

    // ---- fork: s-path fully independent of t-path until attention ----------
    cudaStream_t s1;
    cudaEvent_t eFork, eJoin;
    cudaStreamCreateWithFlags(&s1, cudaStreamNonBlocking);
    cudaEventCreateWithFlags(&eFork, cudaEventDisableTiming);
    cudaEventCreateWithFlags(&eJoin, cudaEventDisableTiming);

    cudaEventRecord(eFork, 0);
    cudaStreamWaitEvent(s1, eFork, 0);

    // stream 0: t-path (cvt xt, cvt Wt, t-proj)
    cvt_h_kernel<<<(BL_*E_/16 + 255)/256, 256>>>(xt, xth, BL_*E_/16);
    cvt_h_kernel<<<(E_*3*E_/16 + 255)/256, 256>>>(Wt, WtT, E_*3*E_/16);
    gemm_h<1><<<dim3(3*E_/128, BL_/128), 256, GEMM_SMEM>>>(
        xth, WtT, bt, nullptr, 3*E_, E_);

    // stream 1: s-path (cvt xs/Ws/Wc, s-proj) — concurrent with t-path
    cvt_h_kernel<<<(BL_*E_/16 + 255)/256, 256, 0, s1>>>(xs, xsh, BL_*E_/16);
    cvt_h_kernel<<<(E_*2*E_/16 + 255)/256, 256, 0, s1>>>(Ws, WsT, E_*2*E_/16);
    cvt_h_kernel<<<(E_*E_/16 + 255)/256, 256, 0, s1>>>(Wc, WcT, E_*E_/16);
    gemm_h<2><<<dim3(2*E_/128, BL_/128), 256, GEMM_SMEM, s1>>>(
        xsh, WsT, bs, nullptr, 2*E_, E_);
    cudaEventRecord(eJoin, s1);

    // join, then attention + out-proj
    cudaStreamWaitEvent(0, eJoin, 0);
    attn_h<<<dim3(L_/128, BH_), 256, ATTN_SMEM>>>(lts, lst, lss);
    gemm_h<0><<<dim3(E_/128, BL_/128), 256, GEMM_SMEM>>>(
        y, WcT, bc, out, E_, E_);

    cudaEventDestroy(eFork);
    cudaEventDestroy(eJoin);
    cudaStreamDestroy(s1);
}